// round 15
// baseline (speedup 1.0000x reference)
#include <cuda_runtime.h>
#include <cuda_bf16.h>
#include <cuda_fp16.h>
#include <math.h>

#define Bq   4
#define Lq   1024
#define Dq   768
#define Hq   12
#define BSq  64
#define Mq   48
#define NEq  24
#define Pq   552
#define Eq   576
#define Rq   97
#define NPq  2208

typedef __nv_bfloat16 bf16;

// ---------------- scratch ----------------
__device__ float g_cur    [Bq*Hq*NEq*Lq];
__device__ float g_ci     [NPq*Dq];
__device__ float g_bh     [NPq*Dq];
__device__ float g_bt     [NPq*Dq];
__device__ int   g_mask   [NPq];
__device__ float g_Ni     [Bq*NEq*Dq];
__device__ float g_Nj     [Bq*NEq*Dq];
__device__ float g_Hs     [Bq*NEq*Dq];
__device__ float g_EfW    [NPq*Dq];
__device__ float g_f      [Bq*Eq*Dq];
__device__ float g_score  [Bq*Eq*Hq];
__device__ float g_alpha  [Bq*Eq*Hq];
__device__ float g_relpart[(size_t)48*NPq*128];
__device__ float g_pairpart[(size_t)4*NPq*Dq];
__device__ int   g_inc    [NEq*23];
__device__ float g_Ebh[96*Dq], g_Ebt[96*Dq], g_Erh[96*Dq], g_Ert[96*Dq];

__device__ bf16 g_enth[Bq*NEq*Dq],   g_entl[Bq*NEq*Dq];
__device__ bf16 g_cah [Bq*Pq*Lq],    g_cal [Bq*Pq*Lq];
__device__ bf16 g_cih [NPq*Dq],      g_cil [NPq*Dq];
__device__ bf16 g_nouth[Bq*NEq*Dq],  g_noutl[Bq*NEq*Dq];
__device__ bf16 g_nch[NPq*Dq],       g_ncl[NPq*Dq];
__device__ bf16 g_ctxh[Bq*Lq*Dq],    g_ctxl[Bq*Lq*Dq];
__device__ bf16 g_Whbh[2*Dq*Dq],     g_Whbl[2*Dq*Dq];
__device__ bf16 g_Wtbh[2*Dq*Dq],     g_Wtbl[2*Dq*Dq];
__device__ bf16 g_Whh [2*Dq*Dq],     g_Whl [2*Dq*Dq];
__device__ bf16 g_Wth [2*Dq*Dq],     g_Wtl [2*Dq*Dq];
__device__ bf16 g_Wfijh[Dq*Dq],      g_Wfijl[Dq*Dq];
__device__ bf16 g_Wnih[Dq*Dq],       g_Wnil[Dq*Dq];
__device__ bf16 g_Wnjh[Dq*Dq],       g_Wnjl[Dq*Dq];
__device__ bf16 g_Wnodeh[Dq*Dq],     g_Wnodel[Dq*Dq];
__device__ __half g_Wpadh[(size_t)Hq*4096*128], g_Wpadl[(size_t)Hq*4096*128];

// ---------------- helpers ----------------
__device__ __forceinline__ void split2(float x, bf16& h, bf16& l) {
    h = __float2bfloat16(x);
    l = __float2bfloat16(x - __bfloat162float(h));
}
__device__ __forceinline__ unsigned su32(const void* p) {
    return (unsigned)__cvta_generic_to_shared(p);
}
__device__ __forceinline__ void ldmx4(unsigned* r, unsigned a) {
    asm volatile("ldmatrix.sync.aligned.m8n8.x4.shared.b16 {%0,%1,%2,%3}, [%4];"
        : "=r"(r[0]), "=r"(r[1]), "=r"(r[2]), "=r"(r[3]) : "r"(a));
}
__device__ __forceinline__ void ldmx4t(unsigned* r, unsigned a) {
    asm volatile("ldmatrix.sync.aligned.m8n8.x4.trans.shared.b16 {%0,%1,%2,%3}, [%4];"
        : "=r"(r[0]), "=r"(r[1]), "=r"(r[2]), "=r"(r[3]) : "r"(a));
}
__device__ __forceinline__ void mma16816(float* c, const unsigned* a, const unsigned* b) {
    asm volatile("mma.sync.aligned.m16n8k16.row.col.f32.bf16.bf16.f32 "
        "{%0,%1,%2,%3}, {%4,%5,%6,%7}, {%8,%9}, {%0,%1,%2,%3};"
        : "+f"(c[0]), "+f"(c[1]), "+f"(c[2]), "+f"(c[3])
        : "r"(a[0]), "r"(a[1]), "r"(a[2]), "r"(a[3]), "r"(b[0]), "r"(b[1]));
}
__device__ __forceinline__ void mma16816f(float* c, const unsigned* a, const unsigned* b) {
    asm volatile("mma.sync.aligned.m16n8k16.row.col.f32.f16.f16.f32 "
        "{%0,%1,%2,%3}, {%4,%5,%6,%7}, {%8,%9}, {%0,%1,%2,%3};"
        : "+f"(c[0]), "+f"(c[1]), "+f"(c[2]), "+f"(c[3])
        : "r"(a[0]), "r"(a[1]), "r"(a[2]), "r"(a[3]), "r"(b[0]), "r"(b[1]));
}

// ---------------- small kernels ----------------
__global__ void k_entity(const float* __restrict__ ctx, const int* __restrict__ mm,
                         const float* __restrict__ em,
                         bf16* __restrict__ oh, bf16* __restrict__ ol)
{
    int bn = blockIdx.x; int b = bn / NEq, n = bn % NEq;
    int d0 = blockIdx.y * 384;
    __shared__ float w_s[Mq]; __shared__ int mi_s[Mq];
    if (threadIdx.x < Mq) {
        w_s[threadIdx.x]  = em[(b*NEq + n)*Mq + threadIdx.x];
        mi_s[threadIdx.x] = mm[b*Mq + threadIdx.x];
    }
    __syncthreads();
    for (int d = d0 + threadIdx.x; d < d0 + 384; d += blockDim.x) {
        float s = 0.f;
        #pragma unroll 4
        for (int m = 0; m < Mq; m++) {
            float w = w_s[m];
            if (w != 0.f) s += w * expf(ctx[((long)b*Lq + mi_s[m])*Dq + d]);
        }
        float v = logf(s);
        bf16 h, l; split2(v, h, l);
        oh[(long)bn*Dq + d] = h; ol[(long)bn*Dq + d] = l;
    }
}

__global__ void k_cur(const float* __restrict__ att, const int* __restrict__ mm,
                      const float* __restrict__ em, float* __restrict__ cur)
{
    int id = blockIdx.x;
    int n = id % NEq; int h = (id / NEq) % Hq; int b = id / (NEq*Hq);
    __shared__ int   act_m[Mq];
    __shared__ float act_w[Mq];
    __shared__ int   nact;
    __shared__ float invc;
    if (threadIdx.x == 0) {
        int c = 0; float cnt = 0.f;
        for (int m = 0; m < Mq; m++) {
            float w = em[(b*NEq + n)*Mq + m]; cnt += w;
            if (w != 0.f) { act_m[c] = mm[b*Mq + m]; act_w[c] = w; c++; }
        }
        nact = c; invc = 1.f / (cnt + 1e-20f);
    }
    __syncthreads();
    const float* abase = att + ((long)(b*Hq + h))*Lq*Lq;
    float* obase = cur + (long)id*Lq;
    int na = nact; float iv = invc;
    for (int l = threadIdx.x; l < Lq; l += blockDim.x) {
        float s = 0.f;
        for (int a = 0; a < na; a++) s += act_w[a] * abase[(long)act_m[a]*Lq + l];
        obase[l] = s * iv;
    }
}

__global__ void k_ca(const float* __restrict__ cur, const int* __restrict__ hts,
                     bf16* __restrict__ cah, bf16* __restrict__ cal)
{
    int bp = blockIdx.x; int b = bp / Pq, p = bp % Pq;
    int h0 = hts[p], h1 = hts[Pq + p];
    const float* c0 = cur + ((long)b*Hq*NEq + h0)*Lq;
    const float* c1 = cur + ((long)b*Hq*NEq + h1)*Lq;
    float v[4]; float local = 0.f;
    #pragma unroll
    for (int q = 0; q < 4; q++) {
        int l = threadIdx.x + q*256;
        float s = 0.f;
        #pragma unroll
        for (int h = 0; h < Hq; h++)
            s += c0[(long)h*NEq*Lq + l] * c1[(long)h*NEq*Lq + l];
        v[q] = s; local += s;
    }
    __shared__ float red[256];
    red[threadIdx.x] = local; __syncthreads();
    for (int off = 128; off > 0; off >>= 1) {
        if (threadIdx.x < off) red[threadIdx.x] += red[threadIdx.x + off];
        __syncthreads();
    }
    float inv = 1.f / (red[0] + 1e-20f);
    #pragma unroll
    for (int q = 0; q < 4; q++) {
        long o = (long)bp*Lq + threadIdx.x + q*256;
        bf16 h, l; split2(v[q]*inv, h, l);
        cah[o] = h; cal[o] = l;
    }
}

__global__ void k_split(const float* __restrict__ src, bf16* __restrict__ hi,
                        bf16* __restrict__ lo, long n)
{
    long i = (long)blockIdx.x*256 + threadIdx.x;
    if (i >= n) return;
    bf16 h, l; split2(src[i], h, l);
    hi[i] = h; lo[i] = l;
}

struct SplitP { const float* s[4]; bf16* h[4]; bf16* l[4]; };
__global__ void k_split4(SplitP p, long n)
{
    long i = (long)blockIdx.x*256 + threadIdx.x;
    if (i >= n) return;
    int z = blockIdx.y;
    float v = p.s[z][i];
    bf16 h, l; split2(v, h, l);
    p.h[z][i] = h; p.l[z][i] = l;
}

__global__ void k_wpadsplit(const float* __restrict__ W, __half* __restrict__ Wh,
                            __half* __restrict__ Wl)
{
    long idx = (long)blockIdx.x*256 + threadIdx.x;
    int o = (int)(idx & 127);
    long row = idx >> 7;
    float v = (o < Rq) ? W[row*Rq + o] : 0.f;
    __half h = __float2half(v);
    __half l = __float2half(v - __half2float(h));
    Wh[idx] = h; Wl[idx] = l;
}

// ---------------- mma.sync GEMM ----------------
// MODE 0: bf16 3-term, A table. MODE 7: K-split partials, raw fp32 store.
struct GemmP {
    const bf16 *Ah[4], *Al[4], *Bh[4], *Bl[4];
    const float* bias[4];
    float* C[4];
    bf16 *Chi[4], *Clo[4];
    const float* Eadd[4];
    int Mz[4];
    const int* hts;
    int K, lda, ldb, ldc, act, splitout;
};

template<int MODE>
__global__ __launch_bounds__(256)
void k_mma(GemmP p)
{
    __shared__ bf16 Ash[128][40], Asl[128][40];
    __shared__ bf16 Bsh[32][136],  Bsl[32][136];

    int z = blockIdx.z;
    int zi = (MODE == 7) ? (z >> 1) : z;
    int ks = (MODE == 7) ? (z & 1) : 0;
    const bf16 *tAh = p.Ah[zi], *tAl = p.Al[zi];
    const bf16 *pBh = p.Bh[zi] + (long)ks*p.K*p.ldb;
    const bf16 *pBl = p.Bl[zi] + (long)ks*p.K*p.ldb;
    float* pC = p.C[z];
    const float* pbias = p.bias[zi];
    int M = p.Mz[zi];
    bf16 *pChi = 0, *pClo = 0;
    if (p.splitout) { pChi = p.Chi[z]; pClo = p.Clo[z]; }

    int row0 = blockIdx.y * 128;
    if (row0 >= M) return;
    int col0 = blockIdx.x * 128;
    int K = p.K, lda = p.lda, ldb = p.ldb, ldc = p.ldc;
    int t = threadIdx.x;

    int arow = t >> 1;
    int ak   = (t & 1) * 16;
    int grow = row0 + arow;
    int rowc = grow < M ? grow : M - 1;
    const bf16 *srcAh0 = tAh + (long)rowc*lda + ks*K;
    const bf16 *srcAl0 = tAl + (long)rowc*lda + ks*K;
    int bk = t >> 3;
    int bn = (t & 7) * 16;

    uint4 vAh0, vAh1, vAl0, vAl1, vBh0, vBh1, vBl0, vBl1;

    #define LOAD_CHUNK(kc) do {                                                     \
        const bf16 *sh = srcAh0 + (kc)*32 + ak, *sl = srcAl0 + (kc)*32 + ak;        \
        vAh0 = *(const uint4*)sh;  vAh1 = *(const uint4*)(sh + 8);                  \
        vAl0 = *(const uint4*)sl;  vAl1 = *(const uint4*)(sl + 8);                  \
        const bf16* bp_ = pBh + (long)((kc)*32 + bk)*ldb + col0 + bn;               \
        const bf16* bq_ = pBl + (long)((kc)*32 + bk)*ldb + col0 + bn;               \
        vBh0 = *(const uint4*)bp_;  vBh1 = *(const uint4*)(bp_ + 8);                \
        vBl0 = *(const uint4*)bq_;  vBl1 = *(const uint4*)(bq_ + 8);                \
    } while (0)

    LOAD_CHUNK(0);

    int w = t >> 5, lane = t & 31;
    int wm = (w >> 1) & 3;
    int wn = (w & 1) ^ ((w >> 2) & 1);
    float acc[2][8][4] = {};

    int KT = K >> 5;
    for (int kc = 0; kc < KT; kc++) {
        *(uint4*)&Ash[arow][ak]     = vAh0;  *(uint4*)&Ash[arow][ak + 8] = vAh1;
        *(uint4*)&Asl[arow][ak]     = vAl0;  *(uint4*)&Asl[arow][ak + 8] = vAl1;
        *(uint4*)&Bsh[bk][bn]       = vBh0;  *(uint4*)&Bsh[bk][bn + 8]   = vBh1;
        *(uint4*)&Bsl[bk][bn]       = vBl0;  *(uint4*)&Bsl[bk][bn + 8]   = vBl1;
        __syncthreads();
        if (kc + 1 < KT) LOAD_CHUNK(kc + 1);

        #pragma unroll
        for (int s = 0; s < 2; s++) {
            unsigned ah[2][4], al[2][4];
            int arw = wm*32 + (lane & 15);
            int acl = s*16 + (lane >> 4)*8;
            ldmx4(ah[0], su32(&Ash[arw][acl]));
            ldmx4(al[0], su32(&Asl[arw][acl]));
            ldmx4(ah[1], su32(&Ash[arw + 16][acl]));
            ldmx4(al[1], su32(&Asl[arw + 16][acl]));
            int brow = s*16 + ((lane >> 3) & 1)*8 + (lane & 7);
            int bcol = wn*64 + (lane >> 4)*8;
            #pragma unroll
            for (int g = 0; g < 4; g++) {
                unsigned bh_[4], bl_[4];
                ldmx4t(bh_, su32(&Bsh[brow][bcol + g*16]));
                ldmx4t(bl_, su32(&Bsl[brow][bcol + g*16]));
                #pragma unroll
                for (int mt = 0; mt < 2; mt++) {
                    mma16816(acc[mt][2*g],   ah[mt], bh_);
                    mma16816(acc[mt][2*g],   ah[mt], bl_);
                    mma16816(acc[mt][2*g],   al[mt], bh_);
                    mma16816(acc[mt][2*g+1], ah[mt], bh_ + 2);
                    mma16816(acc[mt][2*g+1], ah[mt], bl_ + 2);
                    mma16816(acc[mt][2*g+1], al[mt], bh_ + 2);
                }
            }
        }
        __syncthreads();
    }
    #undef LOAD_CHUNK

    int rg = row0 + wm*32 + (lane >> 2);
    int cb = col0 + wn*64 + (lane & 3)*2;
    #pragma unroll
    for (int mt = 0; mt < 2; mt++) {
        #pragma unroll
        for (int n8 = 0; n8 < 8; n8++) {
            int rr = rg + mt*16;
            int cc = cb + n8*8;
            float v0 = acc[mt][n8][0], v1 = acc[mt][n8][1];
            float v2 = acc[mt][n8][2], v3 = acc[mt][n8][3];
            if (MODE != 7 && pbias) {
                float b0 = pbias[cc], b1 = pbias[cc+1];
                v0 += b0; v1 += b1; v2 += b0; v3 += b1;
            }
            if (MODE != 7 && p.act) { v0 = tanhf(v0); v1 = tanhf(v1); v2 = tanhf(v2); v3 = tanhf(v3); }
            if (rr < M) {
                *(float2*)(pC + (long)rr*ldc + cc) = make_float2(v0, v1);
                if (pChi) {
                    bf16 h0,l0,h1,l1; split2(v0,h0,l0); split2(v1,h1,l1);
                    *(__nv_bfloat162*)(pChi + (long)rr*ldc + cc) = __nv_bfloat162(h0, h1);
                    *(__nv_bfloat162*)(pClo + (long)rr*ldc + cc) = __nv_bfloat162(l0, l1);
                }
            }
            if (rr + 8 < M) {
                *(float2*)(pC + (long)(rr+8)*ldc + cc) = make_float2(v2, v3);
                if (pChi) {
                    bf16 h0,l0,h1,l1; split2(v2,h0,l0); split2(v3,h1,l1);
                    *(__nv_bfloat162*)(pChi + (long)(rr+8)*ldc + cc) = __nv_bfloat162(h0, h1);
                    *(__nv_bfloat162*)(pClo + (long)(rr+8)*ldc + cc) = __nv_bfloat162(l0, l1);
                }
            }
        }
    }
}

// epilogue for K-split pair GEMM: out = tanh(pA + pB + Eadd[gather] + bias)
__global__ void k_pairepi(const float* __restrict__ part,
                          const float* __restrict__ Ea0, const float* __restrict__ Ea1,
                          const float* __restrict__ b0p, const float* __restrict__ b1p,
                          const int* __restrict__ hts,
                          float* __restrict__ out0, float* __restrict__ out1)
{
    long idx = (long)blockIdx.x*256 + threadIdx.x;
    int pair = blockIdx.y;
    int d = (int)(idx % Dq); long n = idx / Dq;
    int b = (int)(n / Pq), pp = (int)(n % Pq);
    const float* Ea = pair ? Ea1 : Ea0;
    const float* bi = pair ? b1p : b0p;
    float v = part[(long)(pair*2)*NPq*Dq + idx] + part[(long)(pair*2+1)*NPq*Dq + idx]
            + Ea[((long)(b*NEq) + hts[pair*Pq + pp])*Dq + d] + bi[d];
    (pair ? out1 : out0)[idx] = tanhf(v);
}

// ---------------- rel head: fp16 2-term, 2 blocks/SM, 4-way K-split ----
__global__ __launch_bounds__(256, 2)
void k_mma3(const __half* __restrict__ Wph, const __half* __restrict__ Wpl,
            const float* __restrict__ bhp, const float* __restrict__ btp,
            float* __restrict__ part)
{
    extern __shared__ char dynraw[];
    float* bhF = (float*)dynraw;
    float* btF = bhF + 128*68;
    __half* sAh = (__half*)(dynraw + 69632);
    __half* sBh = (__half*)(dynraw + 69632 + 10240);
    __half* sBl = (__half*)(dynraw + 69632 + 18944);

    int z = blockIdx.z;
    int h3 = z >> 2;
    int kcb = (z & 3) * 32;
    const __half* pBh = Wph + (long)h3*4096*128;
    const __half* pBl = Wpl + (long)h3*4096*128;
    float* pC = part + (long)z*NPq*128;
    int row0 = blockIdx.y * 128;
    int t = threadIdx.x;

    int arow = t >> 1;
    int ak   = (t & 1) * 16;
    int bk = t >> 3;
    int bn = (t & 7) * 16;

    for (int idx = t; idx < 128*16; idx += 256) {
        int r = idx >> 4, q = (idx & 15) * 4;
        int rr = row0 + r; if (rr >= NPq) rr = NPq - 1;
        *(float4*)&bhF[r*68 + q] = *(const float4*)(bhp + (long)rr*Dq + h3*64 + q);
        *(float4*)&btF[r*68 + q] = *(const float4*)(btp + (long)rr*Dq + h3*64 + q);
    }
    __syncthreads();

    uint4 vA0, vA1, vB0, vB1, vB2, vB3;

    #define LOAD_CHUNK3(kc) do {                                                    \
        int kk_ = (kc) + kcb;                                                       \
        int i_ = kk_ >> 1, j0_ = (kk_ & 1) * 32;                                    \
        float a_ = bhF[arow*68 + i_];                                               \
        const float* c_ = btF + arow*68 + j0_ + ak;                                 \
        union { uint4 u; __half2 h2[4]; } ua0, ua1;                                 \
        _Pragma("unroll")                                                           \
        for (int q = 0; q < 4; q++)                                                 \
            ua0.h2[q] = __float22half2_rn(make_float2(a_*c_[2*q], a_*c_[2*q+1]));   \
        _Pragma("unroll")                                                           \
        for (int q = 0; q < 4; q++)                                                 \
            ua1.h2[q] = __float22half2_rn(make_float2(a_*c_[8+2*q], a_*c_[8+2*q+1]));\
        vA0 = ua0.u; vA1 = ua1.u;                                                   \
        const __half* bp_ = pBh + (long)(kk_*32 + bk)*128 + bn;                     \
        const __half* bq_ = pBl + (long)(kk_*32 + bk)*128 + bn;                     \
        vB0 = *(const uint4*)bp_;  vB1 = *(const uint4*)(bp_ + 8);                  \
        vB2 = *(const uint4*)bq_;  vB3 = *(const uint4*)(bq_ + 8);                  \
    } while (0)

    LOAD_CHUNK3(0);

    int w = t >> 5, lane = t & 31;
    int wm = (w >> 1) & 3;
    int wn = (w & 1) ^ ((w >> 2) & 1);
    float acc[2][8][4] = {};

    for (int kc = 0; kc < 32; kc++) {
        *(uint4*)(sAh + arow*40 + ak)   = vA0;  *(uint4*)(sAh + arow*40 + ak + 8) = vA1;
        *(uint4*)(sBh + bk*136 + bn)    = vB0;  *(uint4*)(sBh + bk*136 + bn + 8)  = vB1;
        *(uint4*)(sBl + bk*136 + bn)    = vB2;  *(uint4*)(sBl + bk*136 + bn + 8)  = vB3;
        __syncthreads();
        if (kc + 1 < 32) LOAD_CHUNK3(kc + 1);

        #pragma unroll
        for (int s = 0; s < 2; s++) {
            unsigned ah[2][4];
            int arw = wm*32 + (lane & 15);
            int acl = s*16 + (lane >> 4)*8;
            ldmx4(ah[0], su32(sAh + arw*40 + acl));
            ldmx4(ah[1], su32(sAh + (arw + 16)*40 + acl));
            int brow = s*16 + ((lane >> 3) & 1)*8 + (lane & 7);
            int bcol = wn*64 + (lane >> 4)*8;
            #pragma unroll
            for (int g = 0; g < 4; g++) {
                if (wn == 1 && g == 3) continue;
                unsigned bh_[4], bl_[4];
                ldmx4t(bh_, su32(sBh + brow*136 + bcol + g*16));
                ldmx4t(bl_, su32(sBl + brow*136 + bcol + g*16));
                #pragma unroll
                for (int mt = 0; mt < 2; mt++) {
                    mma16816f(acc[mt][2*g],   ah[mt], bh_);
                    mma16816f(acc[mt][2*g],   ah[mt], bl_);
                    if (!(wn == 1 && g == 2)) {
                        mma16816f(acc[mt][2*g+1], ah[mt], bh_ + 2);
                        mma16816f(acc[mt][2*g+1], ah[mt], bl_ + 2);
                    }
                }
            }
        }
        __syncthreads();
    }
    #undef LOAD_CHUNK3

    int rg = row0 + wm*32 + (lane >> 2);
    int cb = wn*64 + (lane & 3)*2;
    #pragma unroll
    for (int mt = 0; mt < 2; mt++) {
        #pragma unroll
        for (int n8 = 0; n8 < 8; n8++) {
            int rr = rg + mt*16;
            int cc = cb + n8*8;
            if (rr < NPq)
                *(float2*)(pC + (long)rr*128 + cc) = make_float2(acc[mt][n8][0], acc[mt][n8][1]);
            if (rr + 8 < NPq)
                *(float2*)(pC + (long)(rr+8)*128 + cc) = make_float2(acc[mt][n8][2], acc[mt][n8][3]);
        }
    }
}

// ---------------- binary head: 16 rows per block ----------------
__global__ void k_gbl_bin16(const float* __restrict__ A, const float* __restrict__ C,
                            const float* __restrict__ W, const float* __restrict__ bias,
                            float* __restrict__ out, int* __restrict__ mask)
{
    extern __shared__ float sm[];
    float* a_s = sm;
    float* c_s = sm + 16*772;
    int n0 = blockIdx.x * 16;
    int t = threadIdx.x;
    for (int idx = t; idx < 16*192; idx += 256) {
        int r = idx / 192, q = (idx % 192) * 4;
        *(float4*)&a_s[r*772 + q] = *(const float4*)(A + (long)(n0 + r)*Dq + q);
        *(float4*)&c_s[r*772 + q] = *(const float4*)(C + (long)(n0 + r)*Dq + q);
    }
    __syncthreads();
    int nl = t & 15, grp = t >> 4;
    float s0 = 0.f, s1 = 0.f;
    for (int s = 0; s < 48; s++) {
        int hi = grp*48 + s;
        float ai = a_s[nl*772 + hi];
        const float2* w2 = (const float2*)(W + (long)hi*BSq*2);
        const float* cc = c_s + nl*772 + (hi & ~63);
        #pragma unroll 8
        for (int j = 0; j < BSq; j++) {
            float v = ai * cc[j];
            float2 ww = w2[j];
            s0 += v*ww.x; s1 += v*ww.y;
        }
    }
    __shared__ float r0[16][17], r1[16][17];
    r0[grp][nl] = s0; r1[grp][nl] = s1;
    __syncthreads();
    if (t < 16) {
        float b0 = bias[0], b1 = bias[1];
        #pragma unroll
        for (int g = 0; g < 16; g++) { b0 += r0[g][t]; b1 += r1[g][t]; }
        int n = n0 + t;
        out[n*2] = b0; out[n*2+1] = b1;
        mask[n] = (b1 > b0) ? 1 : 0;
    }
}

__global__ void k_inc(const int* __restrict__ hts, int* __restrict__ inc)
{
    if (threadIdx.x == 0 && blockIdx.x == 0) {
        int cnt[NEq];
        for (int i = 0; i < NEq; i++) cnt[i] = 0;
        for (int p = 0; p < Pq; p++) {
            int d = hts[Pq + p];
            inc[d*23 + cnt[d]++] = p;
        }
    }
}

__global__ void k_fscore(const float* __restrict__ Ni, const float* __restrict__ Nj,
                         const float* __restrict__ EfW, const float* __restrict__ eb,
                         const float* __restrict__ attn_p, const int* __restrict__ mask,
                         const int* __restrict__ hts,
                         float* __restrict__ f, float* __restrict__ score)
{
    __shared__ float f_s[Dq];
    int be = blockIdx.x; int b = be / Eq, e = be % Eq;
    int src, dst; const float* ef = 0;
    if (e < Pq) { src = hts[e]; dst = hts[Pq + e]; ef = EfW + ((long)b*Pq + e)*Dq; }
    else        { src = dst = e - Pq; }
    const float* ni = Ni + ((long)b*NEq + src)*Dq;
    const float* nj = Nj + ((long)b*NEq + dst)*Dq;
    float* o = f + (long)be*Dq;
    int t = threadIdx.x;
    for (int d = t; d < Dq; d += 384) {
        float v = ni[d] + nj[d] + eb[d];
        if (ef) v += ef[d];
        f_s[d] = v;
        o[d] = v;
    }
    __syncthreads();
    int h = t >> 5, lane = t & 31;
    const float* fr = f_s + h*BSq;
    float s = 0.f;
    #pragma unroll
    for (int i = lane; i < BSq; i += 32) {
        float x = fr[i];
        float lr = x > 0.f ? x : 0.2f*x;
        s += lr * attn_p[h*BSq + i];
    }
    #pragma unroll
    for (int off = 16; off; off >>= 1) s += __shfl_xor_sync(0xffffffffu, s, off);
    if (lane == 0) {
        int m = (e < Pq) ? mask[b*Pq + e] : 1;
        score[(long)be*Hq + h] = m ? s : -1e30f;
    }
}

__global__ void k_soft(const float* __restrict__ score, const int* __restrict__ inc,
                       const int* __restrict__ mask, float* __restrict__ alpha)
{
    int bn = blockIdx.x; int b = bn / NEq, n = bn % NEq;
    int h = threadIdx.x >> 5, lane = threadIdx.x & 31;
    int eid = 0; float sc = -INFINITY; float m = 0.f;
    if (lane < 24) {
        eid = (lane < 23) ? inc[n*23 + lane] : (Pq + n);
        sc  = score[((long)b*Eq + eid)*Hq + h];
        m   = (eid < Pq) ? (float)mask[b*Pq + eid] : 1.f;
    }
    float mx = sc;
    #pragma unroll
    for (int off = 16; off; off >>= 1) mx = fmaxf(mx, __shfl_xor_sync(0xffffffffu, mx, off));
    float ex = (lane < 24) ? expf(sc - mx)*m : 0.f;
    float den = ex;
    #pragma unroll
    for (int off = 16; off; off >>= 1) den += __shfl_xor_sync(0xffffffffu, den, off);
    if (lane < 24) alpha[((long)b*Eq + eid)*Hq + h] = ex / (den + 1e-20f);
}

__global__ void k_nodeout(const float* __restrict__ alpha, const float* __restrict__ Hsrc,
                          const int* __restrict__ inc, const int* __restrict__ hts,
                          bf16* __restrict__ oh, bf16* __restrict__ ol)
{
    int bn = blockIdx.x; int b = bn / NEq, n = bn % NEq;
    __shared__ int   esrc[24];
    __shared__ float eal[24*Hq];
    int t = threadIdx.x;
    if (t < 24) {
        int eid = (t < 23) ? inc[n*23 + t] : (Pq + n);
        esrc[t] = (t < 23) ? hts[eid] : n;
    }
    for (int t2 = t; t2 < 24*Hq; t2 += blockDim.x) {
        int slot = t2 / Hq, hh = t2 % Hq;
        int eid = (slot < 23) ? inc[n*23 + slot] : (Pq + n);
        eal[t2] = alpha[((long)b*Eq + eid)*Hq + hh];
    }
    __syncthreads();
    for (int d = t; d < Dq; d += blockDim.x) {
        int h = d >> 6;
        float s = 0.f;
        #pragma unroll
        for (int slot = 0; slot < 24; slot++)
            s += eal[slot*Hq + h] * Hsrc[((long)b*NEq + esrc[slot])*Dq + d];
        bf16 hh, ll; split2(s, hh, ll);
        oh[(long)bn*Dq + d] = hh; ol[(long)bn*Dq + d] = ll;
    }
}

__global__ void k_newci(const int* __restrict__ mask, const float* __restrict__ f,
                        const float* __restrict__ ci, bf16* __restrict__ oh,
                        bf16* __restrict__ ol)
{
    long idx = (long)blockIdx.x*256 + threadIdx.x;
    int d = (int)(idx % Dq); long n = idx / Dq;
    int b = (int)(n / Pq), p = (int)(n % Pq);
    float v = mask[n] ? f[((long)b*Eq + p)*Dq + d] : ci[idx];
    bf16 h, l; split2(v, h, l);
    oh[idx] = h; ol[idx] = l;
}

__global__ void k_rel_reduce(const float* __restrict__ part, const float* __restrict__ brel,
                             float* __restrict__ out)
{
    long idx = (long)blockIdx.x*256 + threadIdx.x;
    if (idx >= (long)NPq*Rq) return;
    int o = (int)(idx % Rq);
    long n = idx / Rq;
    float s = brel[o];
    #pragma unroll
    for (int h = 0; h < 48; h++) s += part[((long)h*NPq + n)*128 + o];
    out[idx] = s;
}

// ---------------- host ----------------
template <typename T>
static T* sym(const void* s) { void* p = 0; cudaGetSymbolAddress(&p, s); return (T*)p; }

#define SMEM_REL 97280

extern "C" void kernel_launch(void* const* d_in, const int* in_sizes, int n_in,
                              void* d_out, int out_size)
{
    const float* ctx    = (const float*)d_in[0];
    const float* att    = (const float*)d_in[1];
    const int*   mm     = (const int*)  d_in[2];
    const float* em     = (const float*)d_in[3];
    const int*   hts    = (const int*)  d_in[4];
    const float* Whb    = (const float*)d_in[5];
    const float* bhb    = (const float*)d_in[6];
    const float* Wtb    = (const float*)d_in[7];
    const float* btb    = (const float*)d_in[8];
    const float* Wbin   = (const float*)d_in[9];
    const float* bbin   = (const float*)d_in[10];
    const float* Wrel   = (const float*)d_in[11];
    const float* brel   = (const float*)d_in[12];
    const float* Wh     = (const float*)d_in[13];
    const float* bh     = (const float*)d_in[14];
    const float* Wt     = (const float*)d_in[15];
    const float* bt     = (const float*)d_in[16];
    const float* Wnode  = (const float*)d_in[17];
    const float* Wni    = (const float*)d_in[18];
    const float* Wfij   = (const float*)d_in[19];
    const float* Wnj    = (const float*)d_in[20];
    const float* attn_p = (const float*)d_in[21];
    const float* egat_b = (const float*)d_in[22];

    float* outBin = (float*)d_out;
    float* outRel = outBin + (long)NPq*2;

    float* p_cur   = sym<float>(g_cur);
    float* p_ci    = sym<float>(g_ci);
    float* p_bh    = sym<float>(g_bh);
    float* p_bt    = sym<float>(g_bt);
    int*   p_mask  = sym<int>(g_mask);
    float* p_Ni    = sym<float>(g_Ni);
    float* p_Nj    = sym<float>(g_Nj);
    float* p_Hs    = sym<float>(g_Hs);
    float* p_EfW   = sym<float>(g_EfW);
    float* p_f     = sym<float>(g_f);
    float* p_score = sym<float>(g_score);
    float* p_alpha = sym<float>(g_alpha);
    float* p_rpart = sym<float>(g_relpart);
    float* p_ppart = sym<float>(g_pairpart);
    int*   p_inc   = sym<int>(g_inc);
    float* p_Ebh   = sym<float>(g_Ebh);
    float* p_Ebt   = sym<float>(g_Ebt);
    float* p_Erh   = sym<float>(g_Erh);
    float* p_Ert   = sym<float>(g_Ert);

    bf16 *enth = sym<bf16>(g_enth), *entl = sym<bf16>(g_entl);
    bf16 *cah  = sym<bf16>(g_cah),  *cal  = sym<bf16>(g_cal);
    bf16 *cih  = sym<bf16>(g_cih),  *cil  = sym<bf16>(g_cil);
    bf16 *nouth= sym<bf16>(g_nouth),*noutl= sym<bf16>(g_noutl);
    bf16 *nch  = sym<bf16>(g_nch),  *ncl  = sym<bf16>(g_ncl);
    bf16 *ctxh = sym<bf16>(g_ctxh), *ctxl = sym<bf16>(g_ctxl);
    bf16 *Whbh = sym<bf16>(g_Whbh), *Whbl = sym<bf16>(g_Whbl);
    bf16 *Wtbh = sym<bf16>(g_Wtbh), *Wtbl = sym<bf16>(g_Wtbl);
    bf16 *Whh  = sym<bf16>(g_Whh),  *Whl  = sym<bf16>(g_Whl);
    bf16 *Wth  = sym<bf16>(g_Wth),  *Wtl  = sym<bf16>(g_Wtl);
    bf16 *Wfijh= sym<bf16>(g_Wfijh),*Wfijl= sym<bf16>(g_Wfijl);
    bf16 *Wnih = sym<bf16>(g_Wnih), *Wnil = sym<bf16>(g_Wnil);
    bf16 *Wnjh = sym<bf16>(g_Wnjh), *Wnjl = sym<bf16>(g_Wnjl);
    bf16 *Wnodeh=sym<bf16>(g_Wnodeh),*Wnodel=sym<bf16>(g_Wnodel);
    __half *Wpadh = sym<__half>(g_Wpadh), *Wpadl = sym<__half>(g_Wpadl);

    cudaFuncSetAttribute(k_mma3, cudaFuncAttributeMaxDynamicSharedMemorySize, SMEM_REL);
    cudaFuncSetAttribute(k_gbl_bin16, cudaFuncAttributeMaxDynamicSharedMemorySize, 2*16*772*4);

    static cudaStream_t s1 = 0, s2 = 0;
    static cudaEvent_t ev0 = 0, ev1 = 0, ev2 = 0, ev3 = 0, ev4 = 0, ev5 = 0, ev6 = 0, evE = 0;
    if (!s1) {
        cudaStreamCreateWithFlags(&s1, cudaStreamNonBlocking);
        cudaStreamCreateWithFlags(&s2, cudaStreamNonBlocking);
        cudaEventCreateWithFlags(&ev0, cudaEventDisableTiming);
        cudaEventCreateWithFlags(&ev1, cudaEventDisableTiming);
        cudaEventCreateWithFlags(&ev2, cudaEventDisableTiming);
        cudaEventCreateWithFlags(&ev3, cudaEventDisableTiming);
        cudaEventCreateWithFlags(&ev4, cudaEventDisableTiming);
        cudaEventCreateWithFlags(&ev5, cudaEventDisableTiming);
        cudaEventCreateWithFlags(&ev6, cudaEventDisableTiming);
        cudaEventCreateWithFlags(&evE, cudaEventDisableTiming);
    }

    // ---- fork 1: ctx split + weight conversions on s1 ----
    cudaEventRecord(ev0, 0);
    cudaStreamWaitEvent(s1, ev0, 0);
    k_split<<<(int)(((long)Bq*Lq*Dq + 255)/256), 256, 0, s1>>>(ctx, ctxh, ctxl, (long)Bq*Lq*Dq);
    cudaEventRecord(ev6, s1);
    {
        SplitP sp = {};
        sp.s[0] = Whb; sp.h[0] = Whbh; sp.l[0] = Whbl;
        sp.s[1] = Wtb; sp.h[1] = Wtbh; sp.l[1] = Wtbl;
        sp.s[2] = Wh;  sp.h[2] = Whh;  sp.l[2] = Whl;
        sp.s[3] = Wt;  sp.h[3] = Wth;  sp.l[3] = Wtl;
        k_split4<<<dim3((2*Dq*Dq + 255)/256, 4), 256, 0, s1>>>(sp, (long)2*Dq*Dq);
    }
    {
        SplitP sp = {};
        sp.s[0] = Wfij;  sp.h[0] = Wfijh;  sp.l[0] = Wfijl;
        sp.s[1] = Wni;   sp.h[1] = Wnih;   sp.l[1] = Wnil;
        sp.s[2] = Wnj;   sp.h[2] = Wnjh;   sp.l[2] = Wnjl;
        sp.s[3] = Wnode; sp.h[3] = Wnodeh; sp.l[3] = Wnodel;
        k_split4<<<dim3((Dq*Dq + 255)/256, 4), 256, 0, s1>>>(sp, (long)Dq*Dq);
    }
    k_wpadsplit<<<(int)(((long)Hq*4096*128)/256), 256, 0, s1>>>(Wrel, Wpadh, Wpadl);
    cudaEventRecord(ev1, s1);

    // ---- main: pooling ----
    k_entity<<<dim3(Bq*NEq, 2), 256>>>(ctx, mm, em, enth, entl);
    k_cur<<<Bq*Hq*NEq, 256>>>(att, mm, em, p_cur);
    k_ca<<<Bq*Pq, 256>>>(p_cur, hts, cah, cal);
    k_inc<<<1, 32>>>(hts, p_inc);

    // ---- ci = ca @ ctx (needs ctx split) ----
    cudaStreamWaitEvent(0, ev6, 0);
    {
        GemmP g = {};
        for (int z = 0; z < Bq; z++) {
            g.Ah[z] = cah + (long)z*Pq*Lq;  g.Al[z] = cal + (long)z*Pq*Lq;
            g.Bh[z] = ctxh + (long)z*Lq*Dq; g.Bl[z] = ctxl + (long)z*Lq*Dq;
            g.C[z]  = p_ci + (long)z*Pq*Dq;
            g.Chi[z]= cih  + (long)z*Pq*Dq; g.Clo[z]= cil + (long)z*Pq*Dq;
            g.Mz[z] = Pq;
        }
        g.K = Lq; g.lda = Lq; g.ldb = Dq; g.ldc = Dq; g.splitout = 1;
        k_mma<0><<<dim3(6, 5, 4), 256>>>(g);
    }

    // join weights; fork 2: Ebin + EGAT GEMMs on s2 concurrent with bin chain
    cudaStreamWaitEvent(0, ev1, 0);
    cudaEventRecord(ev2, 0);
    cudaStreamWaitEvent(s2, ev2, 0);
    {
        GemmP g = {};
        g.Ah[0] = enth; g.Al[0] = entl; g.Bh[0] = Whbh; g.Bl[0] = Whbl; g.C[0] = p_Ebh; g.Mz[0] = Bq*NEq;
        g.Ah[1] = enth; g.Al[1] = entl; g.Bh[1] = Wtbh; g.Bl[1] = Wtbl; g.C[1] = p_Ebt; g.Mz[1] = Bq*NEq;
        g.K = Dq; g.lda = Dq; g.ldb = Dq; g.ldc = Dq;
        k_mma<0><<<dim3(6, 1, 2), 256, 0, s2>>>(g);
    }
    cudaEventRecord(evE, s2);
    {
        GemmP g = {};
        g.Ah[0] = cih;  g.Al[0] = cil;  g.Bh[0] = Wfijh;  g.Bl[0] = Wfijl;  g.C[0] = p_EfW; g.Mz[0] = NPq;
        g.Ah[1] = enth; g.Al[1] = entl; g.Bh[1] = Wnih;   g.Bl[1] = Wnil;   g.C[1] = p_Ni;  g.Mz[1] = Bq*NEq;
        g.Ah[2] = enth; g.Al[2] = entl; g.Bh[2] = Wnjh;   g.Bl[2] = Wnjl;   g.C[2] = p_Nj;  g.Mz[2] = Bq*NEq;
        g.Ah[3] = enth; g.Al[3] = entl; g.Bh[3] = Wnodeh; g.Bl[3] = Wnodel; g.C[3] = p_Hs;  g.Mz[3] = Bq*NEq;
        g.K = Dq; g.lda = Dq; g.ldb = Dq; g.ldc = Dq;
        k_mma<0><<<dim3(6, 18, 4), 256, 0, s2>>>(g);
    }
    cudaEventRecord(ev3, s2);

    // ---- main: bin chain (K-split bin pair || Ebin on s2) ----
    {
        GemmP g = {};
        g.Ah[0] = cih; g.Al[0] = cil; g.Bh[0] = Whbh + (long)Dq*Dq; g.Bl[0] = Whbl + (long)Dq*Dq;
        g.Ah[1] = cih; g.Al[1] = cil; g.Bh[1] = Wtbh + (long)Dq*Dq; g.Bl[1] = Wtbl + (long)Dq*Dq;
        g.Mz[0] = NPq; g.Mz[1] = NPq;
        for (int z = 0; z < 4; z++) g.C[z] = p_ppart + (long)z*NPq*Dq;
        g.K = 384; g.lda = Dq; g.ldb = Dq; g.ldc = Dq;
        k_mma<7><<<dim3(6, 18, 4), 256>>>(g);
    }
    cudaStreamWaitEvent(0, evE, 0);
    k_pairepi<<<dim3((int)(((long)NPq*Dq)/256), 2), 256>>>(p_ppart, p_Ebh, p_Ebt, bhb, btb, hts, p_bh, p_bt);
    k_gbl_bin16<<<NPq/16, 256, 2*16*772*4>>>(p_bh, p_bt, Wbin, bbin, outBin, p_mask);

    // join EGAT
    cudaStreamWaitEvent(0, ev3, 0);
    k_fscore<<<Bq*Eq, 384>>>(p_Ni, p_Nj, p_EfW, egat_b, attn_p, p_mask, hts, p_f, p_score);
    // fork 3: newci on s2 concurrent with soft/nodeout/Er
    cudaEventRecord(ev4, 0);
    cudaStreamWaitEvent(s2, ev4, 0);
    k_newci<<<NPq*Dq/256, 256, 0, s2>>>(p_mask, p_f, p_ci, nch, ncl);
    cudaEventRecord(ev5, s2);

    k_soft<<<Bq*NEq, 384>>>(p_score, p_inc, p_mask, p_alpha);
    k_nodeout<<<Bq*NEq, 256>>>(p_alpha, p_Hs, p_inc, hts, nouth, noutl);
    {
        GemmP g = {};
        g.Ah[0] = nouth; g.Al[0] = noutl; g.Bh[0] = Whh; g.Bl[0] = Whl; g.C[0] = p_Erh; g.Mz[0] = Bq*NEq;
        g.Ah[1] = nouth; g.Al[1] = noutl; g.Bh[1] = Wth; g.Bl[1] = Wtl; g.C[1] = p_Ert; g.Mz[1] = Bq*NEq;
        g.K = Dq; g.lda = Dq; g.ldb = Dq; g.ldc = Dq;
        k_mma<0><<<dim3(6, 1, 2), 256>>>(g);
    }
    cudaStreamWaitEvent(0, ev5, 0);

    // ---- rel pair: K-split + epilogue ----
    {
        GemmP g = {};
        g.Ah[0] = nch; g.Al[0] = ncl; g.Bh[0] = Whh + (long)Dq*Dq; g.Bl[0] = Whl + (long)Dq*Dq;
        g.Ah[1] = nch; g.Al[1] = ncl; g.Bh[1] = Wth + (long)Dq*Dq; g.Bl[1] = Wtl + (long)Dq*Dq;
        g.Mz[0] = NPq; g.Mz[1] = NPq;
        for (int z = 0; z < 4; z++) g.C[z] = p_ppart + (long)z*NPq*Dq;
        g.K = 384; g.lda = Dq; g.ldb = Dq; g.ldc = Dq;
        k_mma<7><<<dim3(6, 18, 4), 256>>>(g);
    }
    k_pairepi<<<dim3((int)(((long)NPq*Dq)/256), 2), 256>>>(p_ppart, p_Erh, p_Ert, bh, bt, hts, p_bh, p_bt);

    // ---- rel head: 48 = 12 heads x 4 K-splits; 2 blocks/SM ----
    k_mma3<<<dim3(1, 18, 48), 256, SMEM_REL>>>(Wpadh, Wpadl, p_bh, p_bt, p_rpart);
    k_rel_reduce<<<((long)NPq*Rq + 255)/256, 256>>>(p_rpart, brel, outRel);
}

// round 16
// speedup vs baseline: 1.0048x; 1.0048x over previous
#include <cuda_runtime.h>
#include <cuda_bf16.h>
#include <cuda_fp16.h>
#include <math.h>

#define Bq   4
#define Lq   1024
#define Dq   768
#define Hq   12
#define BSq  64
#define Mq   48
#define NEq  24
#define Pq   552
#define Eq   576
#define Rq   97
#define NPq  2208

typedef __nv_bfloat16 bf16;

// ---------------- scratch ----------------
__device__ float g_cur    [Bq*Hq*NEq*Lq];
__device__ float g_ci     [NPq*Dq];
__device__ float g_bh     [NPq*Dq];
__device__ float g_bt     [NPq*Dq];
__device__ int   g_mask   [NPq];
__device__ float g_Ni     [Bq*NEq*Dq];
__device__ float g_Nj     [Bq*NEq*Dq];
__device__ float g_Hs     [Bq*NEq*Dq];
__device__ float g_EfW    [NPq*Dq];
__device__ float g_f      [Bq*Eq*Dq];
__device__ float g_score  [Bq*Eq*Hq];
__device__ float g_alpha  [Bq*Eq*Hq];
__device__ float g_relpart[(size_t)48*NPq*128];
__device__ float g_pairpart[(size_t)4*NPq*Dq];
__device__ int   g_inc    [NEq*23];
__device__ float g_Ebh[96*Dq], g_Ebt[96*Dq], g_Erh[96*Dq], g_Ert[96*Dq];

__device__ bf16 g_enth[Bq*NEq*Dq],   g_entl[Bq*NEq*Dq];
__device__ bf16 g_cah [Bq*Pq*Lq],    g_cal [Bq*Pq*Lq];
__device__ bf16 g_cih [NPq*Dq],      g_cil [NPq*Dq];
__device__ bf16 g_nouth[Bq*NEq*Dq],  g_noutl[Bq*NEq*Dq];
__device__ bf16 g_nch[NPq*Dq],       g_ncl[NPq*Dq];
__device__ bf16 g_ctxh[Bq*Lq*Dq],    g_ctxl[Bq*Lq*Dq];
__device__ bf16 g_Whbh[2*Dq*Dq],     g_Whbl[2*Dq*Dq];
__device__ bf16 g_Wtbh[2*Dq*Dq],     g_Wtbl[2*Dq*Dq];
__device__ bf16 g_Whh [2*Dq*Dq],     g_Whl [2*Dq*Dq];
__device__ bf16 g_Wth [2*Dq*Dq],     g_Wtl [2*Dq*Dq];
__device__ bf16 g_Wfijh[Dq*Dq],      g_Wfijl[Dq*Dq];
__device__ bf16 g_Wnih[Dq*Dq],       g_Wnil[Dq*Dq];
__device__ bf16 g_Wnjh[Dq*Dq],       g_Wnjl[Dq*Dq];
__device__ bf16 g_Wnodeh[Dq*Dq],     g_Wnodel[Dq*Dq];
__device__ __half g_Wpadh[(size_t)Hq*4096*128], g_Wpadl[(size_t)Hq*4096*128];

// ---------------- helpers ----------------
__device__ __forceinline__ void split2(float x, bf16& h, bf16& l) {
    h = __float2bfloat16(x);
    l = __float2bfloat16(x - __bfloat162float(h));
}
__device__ __forceinline__ unsigned su32(const void* p) {
    return (unsigned)__cvta_generic_to_shared(p);
}
__device__ __forceinline__ void ldmx4(unsigned* r, unsigned a) {
    asm volatile("ldmatrix.sync.aligned.m8n8.x4.shared.b16 {%0,%1,%2,%3}, [%4];"
        : "=r"(r[0]), "=r"(r[1]), "=r"(r[2]), "=r"(r[3]) : "r"(a));
}
__device__ __forceinline__ void ldmx4t(unsigned* r, unsigned a) {
    asm volatile("ldmatrix.sync.aligned.m8n8.x4.trans.shared.b16 {%0,%1,%2,%3}, [%4];"
        : "=r"(r[0]), "=r"(r[1]), "=r"(r[2]), "=r"(r[3]) : "r"(a));
}
__device__ __forceinline__ void mma16816(float* c, const unsigned* a, const unsigned* b) {
    asm volatile("mma.sync.aligned.m16n8k16.row.col.f32.bf16.bf16.f32 "
        "{%0,%1,%2,%3}, {%4,%5,%6,%7}, {%8,%9}, {%0,%1,%2,%3};"
        : "+f"(c[0]), "+f"(c[1]), "+f"(c[2]), "+f"(c[3])
        : "r"(a[0]), "r"(a[1]), "r"(a[2]), "r"(a[3]), "r"(b[0]), "r"(b[1]));
}
__device__ __forceinline__ void mma16816f(float* c, const unsigned* a, const unsigned* b) {
    asm volatile("mma.sync.aligned.m16n8k16.row.col.f32.f16.f16.f32 "
        "{%0,%1,%2,%3}, {%4,%5,%6,%7}, {%8,%9}, {%0,%1,%2,%3};"
        : "+f"(c[0]), "+f"(c[1]), "+f"(c[2]), "+f"(c[3])
        : "r"(a[0]), "r"(a[1]), "r"(a[2]), "r"(a[3]), "r"(b[0]), "r"(b[1]));
}

// ---------------- small kernels ----------------
__global__ void k_entity(const float* __restrict__ ctx, const int* __restrict__ mm,
                         const float* __restrict__ em,
                         bf16* __restrict__ oh, bf16* __restrict__ ol)
{
    int bn = blockIdx.x; int b = bn / NEq, n = bn % NEq;
    __shared__ float w_s[Mq]; __shared__ int mi_s[Mq];
    if (threadIdx.x < Mq) {
        w_s[threadIdx.x]  = em[(b*NEq + n)*Mq + threadIdx.x];
        mi_s[threadIdx.x] = mm[b*Mq + threadIdx.x];
    }
    __syncthreads();
    for (int d = threadIdx.x; d < Dq; d += blockDim.x) {
        float s = 0.f;
        #pragma unroll 4
        for (int m = 0; m < Mq; m++) {
            float w = w_s[m];
            if (w != 0.f) s += w * expf(ctx[((long)b*Lq + mi_s[m])*Dq + d]);
        }
        float v = logf(s);
        bf16 h, l; split2(v, h, l);
        oh[(long)bn*Dq + d] = h; ol[(long)bn*Dq + d] = l;
    }
}

__global__ void k_cur(const float* __restrict__ att, const int* __restrict__ mm,
                      const float* __restrict__ em, float* __restrict__ cur)
{
    int id = blockIdx.x;
    int n = id % NEq; int h = (id / NEq) % Hq; int b = id / (NEq*Hq);
    __shared__ int   act_m[Mq];
    __shared__ float act_w[Mq];
    __shared__ int   nact;
    __shared__ float invc;
    if (threadIdx.x == 0) {
        int c = 0; float cnt = 0.f;
        for (int m = 0; m < Mq; m++) {
            float w = em[(b*NEq + n)*Mq + m]; cnt += w;
            if (w != 0.f) { act_m[c] = mm[b*Mq + m]; act_w[c] = w; c++; }
        }
        nact = c; invc = 1.f / (cnt + 1e-20f);
    }
    __syncthreads();
    const float* abase = att + ((long)(b*Hq + h))*Lq*Lq;
    float* obase = cur + (long)id*Lq;
    int na = nact; float iv = invc;
    for (int l = threadIdx.x; l < Lq; l += blockDim.x) {
        float s = 0.f;
        for (int a = 0; a < na; a++) s += act_w[a] * abase[(long)act_m[a]*Lq + l];
        obase[l] = s * iv;
    }
}

__global__ void k_ca(const float* __restrict__ cur, const int* __restrict__ hts,
                     bf16* __restrict__ cah, bf16* __restrict__ cal)
{
    int bp = blockIdx.x; int b = bp / Pq, p = bp % Pq;
    int h0 = hts[p], h1 = hts[Pq + p];
    const float* c0 = cur + ((long)b*Hq*NEq + h0)*Lq;
    const float* c1 = cur + ((long)b*Hq*NEq + h1)*Lq;
    float v[4]; float local = 0.f;
    #pragma unroll
    for (int q = 0; q < 4; q++) {
        int l = threadIdx.x + q*256;
        float s = 0.f;
        #pragma unroll
        for (int h = 0; h < Hq; h++)
            s += c0[(long)h*NEq*Lq + l] * c1[(long)h*NEq*Lq + l];
        v[q] = s; local += s;
    }
    __shared__ float red[256];
    red[threadIdx.x] = local; __syncthreads();
    for (int off = 128; off > 0; off >>= 1) {
        if (threadIdx.x < off) red[threadIdx.x] += red[threadIdx.x + off];
        __syncthreads();
    }
    float inv = 1.f / (red[0] + 1e-20f);
    #pragma unroll
    for (int q = 0; q < 4; q++) {
        long o = (long)bp*Lq + threadIdx.x + q*256;
        bf16 h, l; split2(v[q]*inv, h, l);
        cah[o] = h; cal[o] = l;
    }
}

__global__ void k_split(const float* __restrict__ src, bf16* __restrict__ hi,
                        bf16* __restrict__ lo, long n)
{
    long i = (long)blockIdx.x*256 + threadIdx.x;
    if (i >= n) return;
    bf16 h, l; split2(src[i], h, l);
    hi[i] = h; lo[i] = l;
}

struct SplitP { const float* s[4]; bf16* h[4]; bf16* l[4]; };
__global__ void k_split4(SplitP p, long n)
{
    long i = (long)blockIdx.x*256 + threadIdx.x;
    if (i >= n) return;
    int z = blockIdx.y;
    float v = p.s[z][i];
    bf16 h, l; split2(v, h, l);
    p.h[z][i] = h; p.l[z][i] = l;
}

__global__ void k_wpadsplit(const float* __restrict__ W, __half* __restrict__ Wh,
                            __half* __restrict__ Wl)
{
    long idx = (long)blockIdx.x*256 + threadIdx.x;
    int o = (int)(idx & 127);
    long row = idx >> 7;
    float v = (o < Rq) ? W[row*Rq + o] : 0.f;
    __half h = __float2half(v);
    __half l = __float2half(v - __half2float(h));
    Wh[idx] = h; Wl[idx] = l;
}

// ---------------- mma.sync GEMM ----------------
// MODE 0: bf16 3-term, A table. MODE 7: K-split partials, raw fp32 store.
struct GemmP {
    const bf16 *Ah[4], *Al[4], *Bh[4], *Bl[4];
    const float* bias[4];
    float* C[4];
    bf16 *Chi[4], *Clo[4];
    const float* Eadd[4];
    int Mz[4];
    const int* hts;
    int K, lda, ldb, ldc, act, splitout;
};

template<int MODE>
__global__ __launch_bounds__(256)
void k_mma(GemmP p)
{
    __shared__ bf16 Ash[128][40], Asl[128][40];
    __shared__ bf16 Bsh[32][136],  Bsl[32][136];

    int z = blockIdx.z;
    int zi = (MODE == 7) ? (z >> 1) : z;
    int ks = (MODE == 7) ? (z & 1) : 0;
    const bf16 *tAh = p.Ah[zi], *tAl = p.Al[zi];
    const bf16 *pBh = p.Bh[zi] + (long)ks*p.K*p.ldb;
    const bf16 *pBl = p.Bl[zi] + (long)ks*p.K*p.ldb;
    float* pC = p.C[z];
    const float* pbias = p.bias[zi];
    int M = p.Mz[zi];
    bf16 *pChi = 0, *pClo = 0;
    if (p.splitout) { pChi = p.Chi[z]; pClo = p.Clo[z]; }

    int row0 = blockIdx.y * 128;
    if (row0 >= M) return;
    int col0 = blockIdx.x * 128;
    int K = p.K, lda = p.lda, ldb = p.ldb, ldc = p.ldc;
    int t = threadIdx.x;

    int arow = t >> 1;
    int ak   = (t & 1) * 16;
    int grow = row0 + arow;
    int rowc = grow < M ? grow : M - 1;
    const bf16 *srcAh0 = tAh + (long)rowc*lda + ks*K;
    const bf16 *srcAl0 = tAl + (long)rowc*lda + ks*K;
    int bk = t >> 3;
    int bn = (t & 7) * 16;

    uint4 vAh0, vAh1, vAl0, vAl1, vBh0, vBh1, vBl0, vBl1;

    #define LOAD_CHUNK(kc) do {                                                     \
        const bf16 *sh = srcAh0 + (kc)*32 + ak, *sl = srcAl0 + (kc)*32 + ak;        \
        vAh0 = *(const uint4*)sh;  vAh1 = *(const uint4*)(sh + 8);                  \
        vAl0 = *(const uint4*)sl;  vAl1 = *(const uint4*)(sl + 8);                  \
        const bf16* bp_ = pBh + (long)((kc)*32 + bk)*ldb + col0 + bn;               \
        const bf16* bq_ = pBl + (long)((kc)*32 + bk)*ldb + col0 + bn;               \
        vBh0 = *(const uint4*)bp_;  vBh1 = *(const uint4*)(bp_ + 8);                \
        vBl0 = *(const uint4*)bq_;  vBl1 = *(const uint4*)(bq_ + 8);                \
    } while (0)

    LOAD_CHUNK(0);

    int w = t >> 5, lane = t & 31;
    int wm = (w >> 1) & 3;
    int wn = (w & 1) ^ ((w >> 2) & 1);
    float acc[2][8][4] = {};

    int KT = K >> 5;
    for (int kc = 0; kc < KT; kc++) {
        *(uint4*)&Ash[arow][ak]     = vAh0;  *(uint4*)&Ash[arow][ak + 8] = vAh1;
        *(uint4*)&Asl[arow][ak]     = vAl0;  *(uint4*)&Asl[arow][ak + 8] = vAl1;
        *(uint4*)&Bsh[bk][bn]       = vBh0;  *(uint4*)&Bsh[bk][bn + 8]   = vBh1;
        *(uint4*)&Bsl[bk][bn]       = vBl0;  *(uint4*)&Bsl[bk][bn + 8]   = vBl1;
        __syncthreads();
        if (kc + 1 < KT) LOAD_CHUNK(kc + 1);

        #pragma unroll
        for (int s = 0; s < 2; s++) {
            unsigned ah[2][4], al[2][4];
            int arw = wm*32 + (lane & 15);
            int acl = s*16 + (lane >> 4)*8;
            ldmx4(ah[0], su32(&Ash[arw][acl]));
            ldmx4(al[0], su32(&Asl[arw][acl]));
            ldmx4(ah[1], su32(&Ash[arw + 16][acl]));
            ldmx4(al[1], su32(&Asl[arw + 16][acl]));
            int brow = s*16 + ((lane >> 3) & 1)*8 + (lane & 7);
            int bcol = wn*64 + (lane >> 4)*8;
            #pragma unroll
            for (int g = 0; g < 4; g++) {
                unsigned bh_[4], bl_[4];
                ldmx4t(bh_, su32(&Bsh[brow][bcol + g*16]));
                ldmx4t(bl_, su32(&Bsl[brow][bcol + g*16]));
                #pragma unroll
                for (int mt = 0; mt < 2; mt++) {
                    mma16816(acc[mt][2*g],   ah[mt], bh_);
                    mma16816(acc[mt][2*g],   ah[mt], bl_);
                    mma16816(acc[mt][2*g],   al[mt], bh_);
                    mma16816(acc[mt][2*g+1], ah[mt], bh_ + 2);
                    mma16816(acc[mt][2*g+1], ah[mt], bl_ + 2);
                    mma16816(acc[mt][2*g+1], al[mt], bh_ + 2);
                }
            }
        }
        __syncthreads();
    }
    #undef LOAD_CHUNK

    int rg = row0 + wm*32 + (lane >> 2);
    int cb = col0 + wn*64 + (lane & 3)*2;
    #pragma unroll
    for (int mt = 0; mt < 2; mt++) {
        #pragma unroll
        for (int n8 = 0; n8 < 8; n8++) {
            int rr = rg + mt*16;
            int cc = cb + n8*8;
            float v0 = acc[mt][n8][0], v1 = acc[mt][n8][1];
            float v2 = acc[mt][n8][2], v3 = acc[mt][n8][3];
            if (MODE != 7 && pbias) {
                float b0 = pbias[cc], b1 = pbias[cc+1];
                v0 += b0; v1 += b1; v2 += b0; v3 += b1;
            }
            if (MODE != 7 && p.act) { v0 = tanhf(v0); v1 = tanhf(v1); v2 = tanhf(v2); v3 = tanhf(v3); }
            if (rr < M) {
                *(float2*)(pC + (long)rr*ldc + cc) = make_float2(v0, v1);
                if (pChi) {
                    bf16 h0,l0,h1,l1; split2(v0,h0,l0); split2(v1,h1,l1);
                    *(__nv_bfloat162*)(pChi + (long)rr*ldc + cc) = __nv_bfloat162(h0, h1);
                    *(__nv_bfloat162*)(pClo + (long)rr*ldc + cc) = __nv_bfloat162(l0, l1);
                }
            }
            if (rr + 8 < M) {
                *(float2*)(pC + (long)(rr+8)*ldc + cc) = make_float2(v2, v3);
                if (pChi) {
                    bf16 h0,l0,h1,l1; split2(v2,h0,l0); split2(v3,h1,l1);
                    *(__nv_bfloat162*)(pChi + (long)(rr+8)*ldc + cc) = __nv_bfloat162(h0, h1);
                    *(__nv_bfloat162*)(pClo + (long)(rr+8)*ldc + cc) = __nv_bfloat162(l0, l1);
                }
            }
        }
    }
}

// epilogue for K-split pair GEMM: out = tanh(pA + pB + Eadd[gather] + bias)
__global__ void k_pairepi(const float* __restrict__ part,
                          const float* __restrict__ Ea0, const float* __restrict__ Ea1,
                          const float* __restrict__ b0p, const float* __restrict__ b1p,
                          const int* __restrict__ hts,
                          float* __restrict__ out0, float* __restrict__ out1)
{
    long idx = (long)blockIdx.x*256 + threadIdx.x;
    int pair = blockIdx.y;
    int d = (int)(idx % Dq); long n = idx / Dq;
    int b = (int)(n / Pq), pp = (int)(n % Pq);
    const float* Ea = pair ? Ea1 : Ea0;
    const float* bi = pair ? b1p : b0p;
    float v = part[(long)(pair*2)*NPq*Dq + idx] + part[(long)(pair*2+1)*NPq*Dq + idx]
            + Ea[((long)(b*NEq) + hts[pair*Pq + pp])*Dq + d] + bi[d];
    (pair ? out1 : out0)[idx] = tanhf(v);
}

// ---------------- rel head: fp16 2-term, 2 blocks/SM, 4-way K-split ----
__global__ __launch_bounds__(256, 2)
void k_mma3(const __half* __restrict__ Wph, const __half* __restrict__ Wpl,
            const float* __restrict__ bhp, const float* __restrict__ btp,
            float* __restrict__ part)
{
    extern __shared__ char dynraw[];
    float* bhF = (float*)dynraw;
    float* btF = bhF + 128*68;
    __half* sAh = (__half*)(dynraw + 69632);
    __half* sBh = (__half*)(dynraw + 69632 + 10240);
    __half* sBl = (__half*)(dynraw + 69632 + 18944);

    int z = blockIdx.z;
    int h3 = z >> 2;
    int kcb = (z & 3) * 32;
    const __half* pBh = Wph + (long)h3*4096*128;
    const __half* pBl = Wpl + (long)h3*4096*128;
    float* pC = part + (long)z*NPq*128;
    int row0 = blockIdx.y * 128;
    int t = threadIdx.x;

    int arow = t >> 1;
    int ak   = (t & 1) * 16;
    int bk = t >> 3;
    int bn = (t & 7) * 16;

    for (int idx = t; idx < 128*16; idx += 256) {
        int r = idx >> 4, q = (idx & 15) * 4;
        int rr = row0 + r; if (rr >= NPq) rr = NPq - 1;
        *(float4*)&bhF[r*68 + q] = *(const float4*)(bhp + (long)rr*Dq + h3*64 + q);
        *(float4*)&btF[r*68 + q] = *(const float4*)(btp + (long)rr*Dq + h3*64 + q);
    }
    __syncthreads();

    uint4 vA0, vA1, vB0, vB1, vB2, vB3;

    #define LOAD_CHUNK3(kc) do {                                                    \
        int kk_ = (kc) + kcb;                                                       \
        int i_ = kk_ >> 1, j0_ = (kk_ & 1) * 32;                                    \
        float a_ = bhF[arow*68 + i_];                                               \
        const float* c_ = btF + arow*68 + j0_ + ak;                                 \
        union { uint4 u; __half2 h2[4]; } ua0, ua1;                                 \
        _Pragma("unroll")                                                           \
        for (int q = 0; q < 4; q++)                                                 \
            ua0.h2[q] = __float22half2_rn(make_float2(a_*c_[2*q], a_*c_[2*q+1]));   \
        _Pragma("unroll")                                                           \
        for (int q = 0; q < 4; q++)                                                 \
            ua1.h2[q] = __float22half2_rn(make_float2(a_*c_[8+2*q], a_*c_[8+2*q+1]));\
        vA0 = ua0.u; vA1 = ua1.u;                                                   \
        const __half* bp_ = pBh + (long)(kk_*32 + bk)*128 + bn;                     \
        const __half* bq_ = pBl + (long)(kk_*32 + bk)*128 + bn;                     \
        vB0 = *(const uint4*)bp_;  vB1 = *(const uint4*)(bp_ + 8);                  \
        vB2 = *(const uint4*)bq_;  vB3 = *(const uint4*)(bq_ + 8);                  \
    } while (0)

    LOAD_CHUNK3(0);

    int w = t >> 5, lane = t & 31;
    int wm = (w >> 1) & 3;
    int wn = (w & 1) ^ ((w >> 2) & 1);
    float acc[2][8][4] = {};

    for (int kc = 0; kc < 32; kc++) {
        *(uint4*)(sAh + arow*40 + ak)   = vA0;  *(uint4*)(sAh + arow*40 + ak + 8) = vA1;
        *(uint4*)(sBh + bk*136 + bn)    = vB0;  *(uint4*)(sBh + bk*136 + bn + 8)  = vB1;
        *(uint4*)(sBl + bk*136 + bn)    = vB2;  *(uint4*)(sBl + bk*136 + bn + 8)  = vB3;
        __syncthreads();
        if (kc + 1 < 32) LOAD_CHUNK3(kc + 1);

        #pragma unroll
        for (int s = 0; s < 2; s++) {
            unsigned ah[2][4];
            int arw = wm*32 + (lane & 15);
            int acl = s*16 + (lane >> 4)*8;
            ldmx4(ah[0], su32(sAh + arw*40 + acl));
            ldmx4(ah[1], su32(sAh + (arw + 16)*40 + acl));
            int brow = s*16 + ((lane >> 3) & 1)*8 + (lane & 7);
            int bcol = wn*64 + (lane >> 4)*8;
            #pragma unroll
            for (int g = 0; g < 4; g++) {
                if (wn == 1 && g == 3) continue;
                unsigned bh_[4], bl_[4];
                ldmx4t(bh_, su32(sBh + brow*136 + bcol + g*16));
                ldmx4t(bl_, su32(sBl + brow*136 + bcol + g*16));
                #pragma unroll
                for (int mt = 0; mt < 2; mt++) {
                    mma16816f(acc[mt][2*g],   ah[mt], bh_);
                    mma16816f(acc[mt][2*g],   ah[mt], bl_);
                    if (!(wn == 1 && g == 2)) {
                        mma16816f(acc[mt][2*g+1], ah[mt], bh_ + 2);
                        mma16816f(acc[mt][2*g+1], ah[mt], bl_ + 2);
                    }
                }
            }
        }
        __syncthreads();
    }
    #undef LOAD_CHUNK3

    int rg = row0 + wm*32 + (lane >> 2);
    int cb = wn*64 + (lane & 3)*2;
    #pragma unroll
    for (int mt = 0; mt < 2; mt++) {
        #pragma unroll
        for (int n8 = 0; n8 < 8; n8++) {
            int rr = rg + mt*16;
            int cc = cb + n8*8;
            if (rr < NPq)
                *(float2*)(pC + (long)rr*128 + cc) = make_float2(acc[mt][n8][0], acc[mt][n8][1]);
            if (rr + 8 < NPq)
                *(float2*)(pC + (long)(rr+8)*128 + cc) = make_float2(acc[mt][n8][2], acc[mt][n8][3]);
        }
    }
}

// ---------------- binary head: 16 rows per block ----------------
__global__ void k_gbl_bin16(const float* __restrict__ A, const float* __restrict__ C,
                            const float* __restrict__ W, const float* __restrict__ bias,
                            float* __restrict__ out, int* __restrict__ mask)
{
    extern __shared__ float sm[];
    float* a_s = sm;
    float* c_s = sm + 16*772;
    int n0 = blockIdx.x * 16;
    int t = threadIdx.x;
    for (int idx = t; idx < 16*192; idx += 256) {
        int r = idx / 192, q = (idx % 192) * 4;
        *(float4*)&a_s[r*772 + q] = *(const float4*)(A + (long)(n0 + r)*Dq + q);
        *(float4*)&c_s[r*772 + q] = *(const float4*)(C + (long)(n0 + r)*Dq + q);
    }
    __syncthreads();
    int nl = t & 15, grp = t >> 4;
    float s0 = 0.f, s1 = 0.f;
    for (int s = 0; s < 48; s++) {
        int hi = grp*48 + s;
        float ai = a_s[nl*772 + hi];
        const float2* w2 = (const float2*)(W + (long)hi*BSq*2);
        const float* cc = c_s + nl*772 + (hi & ~63);
        #pragma unroll 8
        for (int j = 0; j < BSq; j++) {
            float v = ai * cc[j];
            float2 ww = w2[j];
            s0 += v*ww.x; s1 += v*ww.y;
        }
    }
    __shared__ float r0[16][17], r1[16][17];
    r0[grp][nl] = s0; r1[grp][nl] = s1;
    __syncthreads();
    if (t < 16) {
        float b0 = bias[0], b1 = bias[1];
        #pragma unroll
        for (int g = 0; g < 16; g++) { b0 += r0[g][t]; b1 += r1[g][t]; }
        int n = n0 + t;
        out[n*2] = b0; out[n*2+1] = b1;
        mask[n] = (b1 > b0) ? 1 : 0;
    }
}

__global__ void k_inc(const int* __restrict__ hts, int* __restrict__ inc)
{
    if (threadIdx.x == 0 && blockIdx.x == 0) {
        int cnt[NEq];
        for (int i = 0; i < NEq; i++) cnt[i] = 0;
        for (int p = 0; p < Pq; p++) {
            int d = hts[Pq + p];
            inc[d*23 + cnt[d]++] = p;
        }
    }
}

__global__ void k_fscore(const float* __restrict__ Ni, const float* __restrict__ Nj,
                         const float* __restrict__ EfW, const float* __restrict__ eb,
                         const float* __restrict__ attn_p, const int* __restrict__ mask,
                         const int* __restrict__ hts,
                         float* __restrict__ f, float* __restrict__ score)
{
    __shared__ float f_s[Dq];
    int be = blockIdx.x; int b = be / Eq, e = be % Eq;
    int src, dst; const float* ef = 0;
    if (e < Pq) { src = hts[e]; dst = hts[Pq + e]; ef = EfW + ((long)b*Pq + e)*Dq; }
    else        { src = dst = e - Pq; }
    const float* ni = Ni + ((long)b*NEq + src)*Dq;
    const float* nj = Nj + ((long)b*NEq + dst)*Dq;
    float* o = f + (long)be*Dq;
    int t = threadIdx.x;
    for (int d = t; d < Dq; d += 384) {
        float v = ni[d] + nj[d] + eb[d];
        if (ef) v += ef[d];
        f_s[d] = v;
        o[d] = v;
    }
    __syncthreads();
    int h = t >> 5, lane = t & 31;
    const float* fr = f_s + h*BSq;
    float s = 0.f;
    #pragma unroll
    for (int i = lane; i < BSq; i += 32) {
        float x = fr[i];
        float lr = x > 0.f ? x : 0.2f*x;
        s += lr * attn_p[h*BSq + i];
    }
    #pragma unroll
    for (int off = 16; off; off >>= 1) s += __shfl_xor_sync(0xffffffffu, s, off);
    if (lane == 0) {
        int m = (e < Pq) ? mask[b*Pq + e] : 1;
        score[(long)be*Hq + h] = m ? s : -1e30f;
    }
}

__global__ void k_soft(const float* __restrict__ score, const int* __restrict__ inc,
                       const int* __restrict__ mask, float* __restrict__ alpha)
{
    int bn = blockIdx.x; int b = bn / NEq, n = bn % NEq;
    int h = threadIdx.x >> 5, lane = threadIdx.x & 31;
    int eid = 0; float sc = -INFINITY; float m = 0.f;
    if (lane < 24) {
        eid = (lane < 23) ? inc[n*23 + lane] : (Pq + n);
        sc  = score[((long)b*Eq + eid)*Hq + h];
        m   = (eid < Pq) ? (float)mask[b*Pq + eid] : 1.f;
    }
    float mx = sc;
    #pragma unroll
    for (int off = 16; off; off >>= 1) mx = fmaxf(mx, __shfl_xor_sync(0xffffffffu, mx, off));
    float ex = (lane < 24) ? expf(sc - mx)*m : 0.f;
    float den = ex;
    #pragma unroll
    for (int off = 16; off; off >>= 1) den += __shfl_xor_sync(0xffffffffu, den, off);
    if (lane < 24) alpha[((long)b*Eq + eid)*Hq + h] = ex / (den + 1e-20f);
}

__global__ void k_nodeout(const float* __restrict__ alpha, const float* __restrict__ Hsrc,
                          const int* __restrict__ inc, const int* __restrict__ hts,
                          bf16* __restrict__ oh, bf16* __restrict__ ol)
{
    int bn = blockIdx.x; int b = bn / NEq, n = bn % NEq;
    __shared__ int   esrc[24];
    __shared__ float eal[24*Hq];
    int t = threadIdx.x;
    if (t < 24) {
        int eid = (t < 23) ? inc[n*23 + t] : (Pq + n);
        esrc[t] = (t < 23) ? hts[eid] : n;
    }
    for (int t2 = t; t2 < 24*Hq; t2 += blockDim.x) {
        int slot = t2 / Hq, hh = t2 % Hq;
        int eid = (slot < 23) ? inc[n*23 + slot] : (Pq + n);
        eal[t2] = alpha[((long)b*Eq + eid)*Hq + hh];
    }
    __syncthreads();
    for (int d = t; d < Dq; d += blockDim.x) {
        int h = d >> 6;
        float s = 0.f;
        #pragma unroll
        for (int slot = 0; slot < 24; slot++)
            s += eal[slot*Hq + h] * Hsrc[((long)b*NEq + esrc[slot])*Dq + d];
        bf16 hh, ll; split2(s, hh, ll);
        oh[(long)bn*Dq + d] = hh; ol[(long)bn*Dq + d] = ll;
    }
}

__global__ void k_newci(const int* __restrict__ mask, const float* __restrict__ f,
                        const float* __restrict__ ci, bf16* __restrict__ oh,
                        bf16* __restrict__ ol)
{
    long idx = (long)blockIdx.x*256 + threadIdx.x;
    int d = (int)(idx % Dq); long n = idx / Dq;
    int b = (int)(n / Pq), p = (int)(n % Pq);
    float v = mask[n] ? f[((long)b*Eq + p)*Dq + d] : ci[idx];
    bf16 h, l; split2(v, h, l);
    oh[idx] = h; ol[idx] = l;
}

// coalesced reduce: one block per pair-row n; thread = column
__global__ void k_rel_reduce(const float* __restrict__ part, const float* __restrict__ brel,
                             float* __restrict__ out)
{
    int n = blockIdx.x;
    int o = threadIdx.x;             // 128 threads; only o<Rq stored
    const float* src = part + (long)n*128 + o;
    float s = 0.f;
    #pragma unroll
    for (int h = 0; h < 48; h++)
        s += src[(long)h*NPq*128];
    if (o < Rq)
        out[(long)n*Rq + o] = brel[o] + s;
}

// ---------------- host ----------------
template <typename T>
static T* sym(const void* s) { void* p = 0; cudaGetSymbolAddress(&p, s); return (T*)p; }

#define SMEM_REL 97280

extern "C" void kernel_launch(void* const* d_in, const int* in_sizes, int n_in,
                              void* d_out, int out_size)
{
    const float* ctx    = (const float*)d_in[0];
    const float* att    = (const float*)d_in[1];
    const int*   mm     = (const int*)  d_in[2];
    const float* em     = (const float*)d_in[3];
    const int*   hts    = (const int*)  d_in[4];
    const float* Whb    = (const float*)d_in[5];
    const float* bhb    = (const float*)d_in[6];
    const float* Wtb    = (const float*)d_in[7];
    const float* btb    = (const float*)d_in[8];
    const float* Wbin   = (const float*)d_in[9];
    const float* bbin   = (const float*)d_in[10];
    const float* Wrel   = (const float*)d_in[11];
    const float* brel   = (const float*)d_in[12];
    const float* Wh     = (const float*)d_in[13];
    const float* bh     = (const float*)d_in[14];
    const float* Wt     = (const float*)d_in[15];
    const float* bt     = (const float*)d_in[16];
    const float* Wnode  = (const float*)d_in[17];
    const float* Wni    = (const float*)d_in[18];
    const float* Wfij   = (const float*)d_in[19];
    const float* Wnj    = (const float*)d_in[20];
    const float* attn_p = (const float*)d_in[21];
    const float* egat_b = (const float*)d_in[22];

    float* outBin = (float*)d_out;
    float* outRel = outBin + (long)NPq*2;

    float* p_cur   = sym<float>(g_cur);
    float* p_ci    = sym<float>(g_ci);
    float* p_bh    = sym<float>(g_bh);
    float* p_bt    = sym<float>(g_bt);
    int*   p_mask  = sym<int>(g_mask);
    float* p_Ni    = sym<float>(g_Ni);
    float* p_Nj    = sym<float>(g_Nj);
    float* p_Hs    = sym<float>(g_Hs);
    float* p_EfW   = sym<float>(g_EfW);
    float* p_f     = sym<float>(g_f);
    float* p_score = sym<float>(g_score);
    float* p_alpha = sym<float>(g_alpha);
    float* p_rpart = sym<float>(g_relpart);
    float* p_ppart = sym<float>(g_pairpart);
    int*   p_inc   = sym<int>(g_inc);
    float* p_Ebh   = sym<float>(g_Ebh);
    float* p_Ebt   = sym<float>(g_Ebt);
    float* p_Erh   = sym<float>(g_Erh);
    float* p_Ert   = sym<float>(g_Ert);

    bf16 *enth = sym<bf16>(g_enth), *entl = sym<bf16>(g_entl);
    bf16 *cah  = sym<bf16>(g_cah),  *cal  = sym<bf16>(g_cal);
    bf16 *cih  = sym<bf16>(g_cih),  *cil  = sym<bf16>(g_cil);
    bf16 *nouth= sym<bf16>(g_nouth),*noutl= sym<bf16>(g_noutl);
    bf16 *nch  = sym<bf16>(g_nch),  *ncl  = sym<bf16>(g_ncl);
    bf16 *ctxh = sym<bf16>(g_ctxh), *ctxl = sym<bf16>(g_ctxl);
    bf16 *Whbh = sym<bf16>(g_Whbh), *Whbl = sym<bf16>(g_Whbl);
    bf16 *Wtbh = sym<bf16>(g_Wtbh), *Wtbl = sym<bf16>(g_Wtbl);
    bf16 *Whh  = sym<bf16>(g_Whh),  *Whl  = sym<bf16>(g_Whl);
    bf16 *Wth  = sym<bf16>(g_Wth),  *Wtl  = sym<bf16>(g_Wtl);
    bf16 *Wfijh= sym<bf16>(g_Wfijh),*Wfijl= sym<bf16>(g_Wfijl);
    bf16 *Wnih = sym<bf16>(g_Wnih), *Wnil = sym<bf16>(g_Wnil);
    bf16 *Wnjh = sym<bf16>(g_Wnjh), *Wnjl = sym<bf16>(g_Wnjl);
    bf16 *Wnodeh=sym<bf16>(g_Wnodeh),*Wnodel=sym<bf16>(g_Wnodel);
    __half *Wpadh = sym<__half>(g_Wpadh), *Wpadl = sym<__half>(g_Wpadl);

    cudaFuncSetAttribute(k_mma3, cudaFuncAttributeMaxDynamicSharedMemorySize, SMEM_REL);
    cudaFuncSetAttribute(k_gbl_bin16, cudaFuncAttributeMaxDynamicSharedMemorySize, 2*16*772*4);

    static cudaStream_t s1 = 0, s2 = 0;
    static cudaEvent_t ev0 = 0, ev1 = 0, ev2 = 0, ev3 = 0, ev4 = 0, ev5 = 0, ev6 = 0, evE = 0;
    if (!s1) {
        cudaStreamCreateWithFlags(&s1, cudaStreamNonBlocking);
        cudaStreamCreateWithFlags(&s2, cudaStreamNonBlocking);
        cudaEventCreateWithFlags(&ev0, cudaEventDisableTiming);
        cudaEventCreateWithFlags(&ev1, cudaEventDisableTiming);
        cudaEventCreateWithFlags(&ev2, cudaEventDisableTiming);
        cudaEventCreateWithFlags(&ev3, cudaEventDisableTiming);
        cudaEventCreateWithFlags(&ev4, cudaEventDisableTiming);
        cudaEventCreateWithFlags(&ev5, cudaEventDisableTiming);
        cudaEventCreateWithFlags(&ev6, cudaEventDisableTiming);
        cudaEventCreateWithFlags(&evE, cudaEventDisableTiming);
    }

    // ---- fork 1: ctx split + weight conversions on s1 ----
    cudaEventRecord(ev0, 0);
    cudaStreamWaitEvent(s1, ev0, 0);
    k_split<<<(int)(((long)Bq*Lq*Dq + 255)/256), 256, 0, s1>>>(ctx, ctxh, ctxl, (long)Bq*Lq*Dq);
    cudaEventRecord(ev6, s1);
    {
        SplitP sp = {};
        sp.s[0] = Whb; sp.h[0] = Whbh; sp.l[0] = Whbl;
        sp.s[1] = Wtb; sp.h[1] = Wtbh; sp.l[1] = Wtbl;
        sp.s[2] = Wh;  sp.h[2] = Whh;  sp.l[2] = Whl;
        sp.s[3] = Wt;  sp.h[3] = Wth;  sp.l[3] = Wtl;
        k_split4<<<dim3((2*Dq*Dq + 255)/256, 4), 256, 0, s1>>>(sp, (long)2*Dq*Dq);
    }
    {
        SplitP sp = {};
        sp.s[0] = Wfij;  sp.h[0] = Wfijh;  sp.l[0] = Wfijl;
        sp.s[1] = Wni;   sp.h[1] = Wnih;   sp.l[1] = Wnil;
        sp.s[2] = Wnj;   sp.h[2] = Wnjh;   sp.l[2] = Wnjl;
        sp.s[3] = Wnode; sp.h[3] = Wnodeh; sp.l[3] = Wnodel;
        k_split4<<<dim3((Dq*Dq + 255)/256, 4), 256, 0, s1>>>(sp, (long)Dq*Dq);
    }
    k_wpadsplit<<<(int)(((long)Hq*4096*128)/256), 256, 0, s1>>>(Wrel, Wpadh, Wpadl);
    cudaEventRecord(ev1, s1);

    // ---- main: pooling ----
    k_entity<<<Bq*NEq, 256>>>(ctx, mm, em, enth, entl);
    k_cur<<<Bq*Hq*NEq, 256>>>(att, mm, em, p_cur);
    k_ca<<<Bq*Pq, 256>>>(p_cur, hts, cah, cal);
    k_inc<<<1, 32>>>(hts, p_inc);

    // ---- ci = ca @ ctx (needs ctx split) ----
    cudaStreamWaitEvent(0, ev6, 0);
    {
        GemmP g = {};
        for (int z = 0; z < Bq; z++) {
            g.Ah[z] = cah + (long)z*Pq*Lq;  g.Al[z] = cal + (long)z*Pq*Lq;
            g.Bh[z] = ctxh + (long)z*Lq*Dq; g.Bl[z] = ctxl + (long)z*Lq*Dq;
            g.C[z]  = p_ci + (long)z*Pq*Dq;
            g.Chi[z]= cih  + (long)z*Pq*Dq; g.Clo[z]= cil + (long)z*Pq*Dq;
            g.Mz[z] = Pq;
        }
        g.K = Lq; g.lda = Lq; g.ldb = Dq; g.ldc = Dq; g.splitout = 1;
        k_mma<0><<<dim3(6, 5, 4), 256>>>(g);
    }

    // join weights; fork 2: EGAT GEMM on s2 concurrent with bin chain
    cudaStreamWaitEvent(0, ev1, 0);
    cudaEventRecord(ev2, 0);
    cudaStreamWaitEvent(s2, ev2, 0);
    {
        GemmP g = {};
        g.Ah[0] = cih;  g.Al[0] = cil;  g.Bh[0] = Wfijh;  g.Bl[0] = Wfijl;  g.C[0] = p_EfW; g.Mz[0] = NPq;
        g.Ah[1] = enth; g.Al[1] = entl; g.Bh[1] = Wnih;   g.Bl[1] = Wnil;   g.C[1] = p_Ni;  g.Mz[1] = Bq*NEq;
        g.Ah[2] = enth; g.Al[2] = entl; g.Bh[2] = Wnjh;   g.Bl[2] = Wnjl;   g.C[2] = p_Nj;  g.Mz[2] = Bq*NEq;
        g.Ah[3] = enth; g.Al[3] = entl; g.Bh[3] = Wnodeh; g.Bl[3] = Wnodel; g.C[3] = p_Hs;  g.Mz[3] = Bq*NEq;
        g.K = Dq; g.lda = Dq; g.ldb = Dq; g.ldc = Dq;
        k_mma<0><<<dim3(6, 18, 4), 256, 0, s2>>>(g);
    }
    cudaEventRecord(ev3, s2);

    // ---- main: bin chain ----
    {
        GemmP g = {};
        g.Ah[0] = enth; g.Al[0] = entl; g.Bh[0] = Whbh; g.Bl[0] = Whbl; g.C[0] = p_Ebh; g.Mz[0] = Bq*NEq;
        g.Ah[1] = enth; g.Al[1] = entl; g.Bh[1] = Wtbh; g.Bl[1] = Wtbl; g.C[1] = p_Ebt; g.Mz[1] = Bq*NEq;
        g.K = Dq; g.lda = Dq; g.ldb = Dq; g.ldc = Dq;
        k_mma<0><<<dim3(6, 1, 2), 256>>>(g);
    }
    {
        GemmP g = {};
        g.Ah[0] = cih; g.Al[0] = cil; g.Bh[0] = Whbh + (long)Dq*Dq; g.Bl[0] = Whbl + (long)Dq*Dq;
        g.Ah[1] = cih; g.Al[1] = cil; g.Bh[1] = Wtbh + (long)Dq*Dq; g.Bl[1] = Wtbl + (long)Dq*Dq;
        g.Mz[0] = NPq; g.Mz[1] = NPq;
        for (int z = 0; z < 4; z++) g.C[z] = p_ppart + (long)z*NPq*Dq;
        g.K = 384; g.lda = Dq; g.ldb = Dq; g.ldc = Dq;
        k_mma<7><<<dim3(6, 18, 4), 256>>>(g);
    }
    k_pairepi<<<dim3((int)(((long)NPq*Dq)/256), 2), 256>>>(p_ppart, p_Ebh, p_Ebt, bhb, btb, hts, p_bh, p_bt);
    k_gbl_bin16<<<NPq/16, 256, 2*16*772*4>>>(p_bh, p_bt, Wbin, bbin, outBin, p_mask);

    // join EGAT
    cudaStreamWaitEvent(0, ev3, 0);
    k_fscore<<<Bq*Eq, 384>>>(p_Ni, p_Nj, p_EfW, egat_b, attn_p, p_mask, hts, p_f, p_score);
    // fork 3: newci on s2 concurrent with soft/nodeout/Er
    cudaEventRecord(ev4, 0);
    cudaStreamWaitEvent(s2, ev4, 0);
    k_newci<<<NPq*Dq/256, 256, 0, s2>>>(p_mask, p_f, p_ci, nch, ncl);
    cudaEventRecord(ev5, s2);

    k_soft<<<Bq*NEq, 384>>>(p_score, p_inc, p_mask, p_alpha);
    k_nodeout<<<Bq*NEq, 256>>>(p_alpha, p_Hs, p_inc, hts, nouth, noutl);
    {
        GemmP g = {};
        g.Ah[0] = nouth; g.Al[0] = noutl; g.Bh[0] = Whh; g.Bl[0] = Whl; g.C[0] = p_Erh; g.Mz[0] = Bq*NEq;
        g.Ah[1] = nouth; g.Al[1] = noutl; g.Bh[1] = Wth; g.Bl[1] = Wtl; g.C[1] = p_Ert; g.Mz[1] = Bq*NEq;
        g.K = Dq; g.lda = Dq; g.ldb = Dq; g.ldc = Dq;
        k_mma<0><<<dim3(6, 1, 2), 256>>>(g);
    }
    cudaStreamWaitEvent(0, ev5, 0);

    // ---- rel pair: K-split + epilogue ----
    {
        GemmP g = {};
        g.Ah[0] = nch; g.Al[0] = ncl; g.Bh[0] = Whh + (long)Dq*Dq; g.Bl[0] = Whl + (long)Dq*Dq;
        g.Ah[1] = nch; g.Al[1] = ncl; g.Bh[1] = Wth + (long)Dq*Dq; g.Bl[1] = Wtl + (long)Dq*Dq;
        g.Mz[0] = NPq; g.Mz[1] = NPq;
        for (int z = 0; z < 4; z++) g.C[z] = p_ppart + (long)z*NPq*Dq;
        g.K = 384; g.lda = Dq; g.ldb = Dq; g.ldc = Dq;
        k_mma<7><<<dim3(6, 18, 4), 256>>>(g);
    }
    k_pairepi<<<dim3((int)(((long)NPq*Dq)/256), 2), 256>>>(p_ppart, p_Erh, p_Ert, bh, bt, hts, p_bh, p_bt);

    // ---- rel head: 48 = 12 heads x 4 K-splits; 2 blocks/SM ----
    k_mma3<<<dim3(1, 18, 48), 256, SMEM_REL>>>(Wpadh, Wpadl, p_bh, p_bt, p_rpart);
    k_rel_reduce<<<NPq, 128>>>(p_rpart, brel, outRel);
}

// round 17
// speedup vs baseline: 1.0223x; 1.0174x over previous
#include <cuda_runtime.h>
#include <cuda_bf16.h>
#include <cuda_fp16.h>
#include <math.h>

#define Bq   4
#define Lq   1024
#define Dq   768
#define Hq   12
#define BSq  64
#define Mq   48
#define NEq  24
#define Pq   552
#define Eq   576
#define Rq   97
#define NPq  2208

typedef __nv_bfloat16 bf16;

// ---------------- scratch ----------------
__device__ float g_cur    [Bq*Hq*NEq*Lq];
__device__ float g_ci     [NPq*Dq];
__device__ float g_bh     [NPq*Dq];
__device__ float g_bt     [NPq*Dq];
__device__ int   g_mask   [NPq];
__device__ float g_Ni     [Bq*NEq*Dq];
__device__ float g_Nj     [Bq*NEq*Dq];
__device__ float g_Hs     [Bq*NEq*Dq];
__device__ float g_EfW    [NPq*Dq];
__device__ float g_f      [Bq*Eq*Dq];
__device__ float g_score  [Bq*Eq*Hq];
__device__ float g_alpha  [Bq*Eq*Hq];
__device__ float g_pairpart[(size_t)4*NPq*Dq];
__device__ int   g_inc    [NEq*23];
__device__ float g_EA0[96*Dq], g_EA1[96*Dq], g_EB0[96*Dq], g_EB1[96*Dq];

__device__ bf16 g_enth[Bq*NEq*Dq],   g_entl[Bq*NEq*Dq];
__device__ bf16 g_cah [Bq*Pq*Lq],    g_cal [Bq*Pq*Lq];
__device__ bf16 g_cih [NPq*Dq],      g_cil [NPq*Dq];
__device__ bf16 g_nouth[Bq*NEq*Dq],  g_noutl[Bq*NEq*Dq];
__device__ bf16 g_nch[NPq*Dq],       g_ncl[NPq*Dq];
__device__ bf16 g_ctxh[Bq*Lq*Dq],    g_ctxl[Bq*Lq*Dq];
__device__ bf16 g_Whbh[2*Dq*Dq],     g_Whbl[2*Dq*Dq];
__device__ bf16 g_Wtbh[2*Dq*Dq],     g_Wtbl[2*Dq*Dq];
__device__ bf16 g_Whh [2*Dq*Dq],     g_Whl [2*Dq*Dq];
__device__ bf16 g_Wth [2*Dq*Dq],     g_Wtl [2*Dq*Dq];
__device__ bf16 g_Wfijh[Dq*Dq],      g_Wfijl[Dq*Dq];
__device__ bf16 g_Wnih[Dq*Dq],       g_Wnil[Dq*Dq];
__device__ bf16 g_Wnjh[Dq*Dq],       g_Wnjl[Dq*Dq];
__device__ bf16 g_Wnodeh[Dq*Dq],     g_Wnodel[Dq*Dq];
__device__ __half g_Wpadh[(size_t)Hq*4096*128], g_Wpadl[(size_t)Hq*4096*128];

// ---------------- helpers ----------------
__device__ __forceinline__ void split2(float x, bf16& h, bf16& l) {
    h = __float2bfloat16(x);
    l = __float2bfloat16(x - __bfloat162float(h));
}
__device__ __forceinline__ unsigned su32(const void* p) {
    return (unsigned)__cvta_generic_to_shared(p);
}
__device__ __forceinline__ void ldmx4(unsigned* r, unsigned a) {
    asm volatile("ldmatrix.sync.aligned.m8n8.x4.shared.b16 {%0,%1,%2,%3}, [%4];"
        : "=r"(r[0]), "=r"(r[1]), "=r"(r[2]), "=r"(r[3]) : "r"(a));
}
__device__ __forceinline__ void ldmx4t(unsigned* r, unsigned a) {
    asm volatile("ldmatrix.sync.aligned.m8n8.x4.trans.shared.b16 {%0,%1,%2,%3}, [%4];"
        : "=r"(r[0]), "=r"(r[1]), "=r"(r[2]), "=r"(r[3]) : "r"(a));
}
__device__ __forceinline__ void mma16816(float* c, const unsigned* a, const unsigned* b) {
    asm volatile("mma.sync.aligned.m16n8k16.row.col.f32.bf16.bf16.f32 "
        "{%0,%1,%2,%3}, {%4,%5,%6,%7}, {%8,%9}, {%0,%1,%2,%3};"
        : "+f"(c[0]), "+f"(c[1]), "+f"(c[2]), "+f"(c[3])
        : "r"(a[0]), "r"(a[1]), "r"(a[2]), "r"(a[3]), "r"(b[0]), "r"(b[1]));
}
__device__ __forceinline__ void mma16816f(float* c, const unsigned* a, const unsigned* b) {
    asm volatile("mma.sync.aligned.m16n8k16.row.col.f32.f16.f16.f32 "
        "{%0,%1,%2,%3}, {%4,%5,%6,%7}, {%8,%9}, {%0,%1,%2,%3};"
        : "+f"(c[0]), "+f"(c[1]), "+f"(c[2]), "+f"(c[3])
        : "r"(a[0]), "r"(a[1]), "r"(a[2]), "r"(a[3]), "r"(b[0]), "r"(b[1]));
}

// ---------------- small kernels ----------------
__global__ void k_entity(const float* __restrict__ ctx, const int* __restrict__ mm,
                         const float* __restrict__ em,
                         bf16* __restrict__ oh, bf16* __restrict__ ol)
{
    int bn = blockIdx.x; int b = bn / NEq, n = bn % NEq;
    __shared__ float w_s[Mq]; __shared__ int mi_s[Mq];
    if (threadIdx.x < Mq) {
        w_s[threadIdx.x]  = em[(b*NEq + n)*Mq + threadIdx.x];
        mi_s[threadIdx.x] = mm[b*Mq + threadIdx.x];
    }
    __syncthreads();
    for (int d = threadIdx.x; d < Dq; d += blockDim.x) {
        float s = 0.f;
        #pragma unroll 4
        for (int m = 0; m < Mq; m++) {
            float w = w_s[m];
            if (w != 0.f) s += w * expf(ctx[((long)b*Lq + mi_s[m])*Dq + d]);
        }
        float v = logf(s);
        bf16 h, l; split2(v, h, l);
        oh[(long)bn*Dq + d] = h; ol[(long)bn*Dq + d] = l;
    }
}

__global__ void k_cur(const float* __restrict__ att, const int* __restrict__ mm,
                      const float* __restrict__ em, float* __restrict__ cur)
{
    int id = blockIdx.x;
    int n = id % NEq; int h = (id / NEq) % Hq; int b = id / (NEq*Hq);
    __shared__ int   act_m[Mq];
    __shared__ float act_w[Mq];
    __shared__ int   nact;
    __shared__ float invc;
    if (threadIdx.x == 0) {
        int c = 0; float cnt = 0.f;
        for (int m = 0; m < Mq; m++) {
            float w = em[(b*NEq + n)*Mq + m]; cnt += w;
            if (w != 0.f) { act_m[c] = mm[b*Mq + m]; act_w[c] = w; c++; }
        }
        nact = c; invc = 1.f / (cnt + 1e-20f);
    }
    __syncthreads();
    const float* abase = att + ((long)(b*Hq + h))*Lq*Lq;
    float* obase = cur + (long)id*Lq;
    int na = nact; float iv = invc;
    for (int l = threadIdx.x; l < Lq; l += blockDim.x) {
        float s = 0.f;
        for (int a = 0; a < na; a++) s += act_w[a] * abase[(long)act_m[a]*Lq + l];
        obase[l] = s * iv;
    }
}

__global__ void k_ca(const float* __restrict__ cur, const int* __restrict__ hts,
                     bf16* __restrict__ cah, bf16* __restrict__ cal)
{
    int bp = blockIdx.x; int b = bp / Pq, p = bp % Pq;
    int h0 = hts[p], h1 = hts[Pq + p];
    const float* c0 = cur + ((long)b*Hq*NEq + h0)*Lq;
    const float* c1 = cur + ((long)b*Hq*NEq + h1)*Lq;
    float v[4]; float local = 0.f;
    #pragma unroll
    for (int q = 0; q < 4; q++) {
        int l = threadIdx.x + q*256;
        float s = 0.f;
        #pragma unroll
        for (int h = 0; h < Hq; h++)
            s += c0[(long)h*NEq*Lq + l] * c1[(long)h*NEq*Lq + l];
        v[q] = s; local += s;
    }
    __shared__ float red[256];
    red[threadIdx.x] = local; __syncthreads();
    for (int off = 128; off > 0; off >>= 1) {
        if (threadIdx.x < off) red[threadIdx.x] += red[threadIdx.x + off];
        __syncthreads();
    }
    float inv = 1.f / (red[0] + 1e-20f);
    #pragma unroll
    for (int q = 0; q < 4; q++) {
        long o = (long)bp*Lq + threadIdx.x + q*256;
        bf16 h, l; split2(v[q]*inv, h, l);
        cah[o] = h; cal[o] = l;
    }
}

__global__ void k_split(const float* __restrict__ src, bf16* __restrict__ hi,
                        bf16* __restrict__ lo, long n)
{
    long i = (long)blockIdx.x*256 + threadIdx.x;
    if (i >= n) return;
    bf16 h, l; split2(src[i], h, l);
    hi[i] = h; lo[i] = l;
}

struct SplitP { const float* s[4]; bf16* h[4]; bf16* l[4]; };
__global__ void k_split4(SplitP p, long n)
{
    long i = (long)blockIdx.x*256 + threadIdx.x;
    if (i >= n) return;
    int z = blockIdx.y;
    float v = p.s[z][i];
    bf16 h, l; split2(v, h, l);
    p.h[z][i] = h; p.l[z][i] = l;
}

__global__ void k_wpadsplit(const float* __restrict__ W, __half* __restrict__ Wh,
                            __half* __restrict__ Wl)
{
    long idx = (long)blockIdx.x*256 + threadIdx.x;
    int o = (int)(idx & 127);
    long row = idx >> 7;
    float v = (o < Rq) ? W[row*Rq + o] : 0.f;
    __half h = __float2half(v);
    __half l = __float2half(v - __half2float(h));
    Wh[idx] = h; Wl[idx] = l;
}

// init outRel with bias
__global__ void k_binit(const float* __restrict__ brel, float* __restrict__ out)
{
    long idx = (long)blockIdx.x*256 + threadIdx.x;
    if (idx >= (long)NPq*Rq) return;
    out[idx] = brel[idx % Rq];
}

// ---------------- mma.sync GEMM ----------------
// MODE 0: bf16 3-term, A table (z<4). MODE 7: K-split partials, raw fp32 store;
//   z = zi*2 + ks, zi<4 tables, C[8] output slices; zi>=2 are small-M addend GEMMs.
struct GemmP {
    const bf16 *Ah[4], *Al[4], *Bh[4], *Bl[4];
    const float* bias[4];
    float* C[8];
    bf16 *Chi[4], *Clo[4];
    int Mz[4];
    int K, lda, ldb, ldc, act, splitout;
};

template<int MODE>
__global__ __launch_bounds__(256)
void k_mma(GemmP p)
{
    __shared__ bf16 Ash[128][40], Asl[128][40];
    __shared__ bf16 Bsh[32][136],  Bsl[32][136];

    int z = blockIdx.z;
    int zi = (MODE == 7) ? (z >> 1) : z;
    int ks = (MODE == 7) ? (z & 1) : 0;
    const bf16 *tAh = p.Ah[zi], *tAl = p.Al[zi];
    const bf16 *pBh = p.Bh[zi] + (long)ks*p.K*p.ldb;
    const bf16 *pBl = p.Bl[zi] + (long)ks*p.K*p.ldb;
    float* pC = p.C[z];
    const float* pbias = p.bias[zi];
    int M = p.Mz[zi];
    bf16 *pChi = 0, *pClo = 0;
    if (p.splitout) { pChi = p.Chi[z]; pClo = p.Clo[z]; }

    int row0 = blockIdx.y * 128;
    if (row0 >= M) return;
    int col0 = blockIdx.x * 128;
    int K = p.K, lda = p.lda, ldb = p.ldb, ldc = p.ldc;
    int t = threadIdx.x;

    int arow = t >> 1;
    int ak   = (t & 1) * 16;
    int grow = row0 + arow;
    int rowc = grow < M ? grow : M - 1;
    const bf16 *srcAh0 = tAh + (long)rowc*lda + ks*K;
    const bf16 *srcAl0 = tAl + (long)rowc*lda + ks*K;
    int bk = t >> 3;
    int bn = (t & 7) * 16;

    uint4 vAh0, vAh1, vAl0, vAl1, vBh0, vBh1, vBl0, vBl1;

    #define LOAD_CHUNK(kc) do {                                                     \
        const bf16 *sh = srcAh0 + (kc)*32 + ak, *sl = srcAl0 + (kc)*32 + ak;        \
        vAh0 = *(const uint4*)sh;  vAh1 = *(const uint4*)(sh + 8);                  \
        vAl0 = *(const uint4*)sl;  vAl1 = *(const uint4*)(sl + 8);                  \
        const bf16* bp_ = pBh + (long)((kc)*32 + bk)*ldb + col0 + bn;               \
        const bf16* bq_ = pBl + (long)((kc)*32 + bk)*ldb + col0 + bn;               \
        vBh0 = *(const uint4*)bp_;  vBh1 = *(const uint4*)(bp_ + 8);                \
        vBl0 = *(const uint4*)bq_;  vBl1 = *(const uint4*)(bq_ + 8);                \
    } while (0)

    LOAD_CHUNK(0);

    int w = t >> 5, lane = t & 31;
    int wm = (w >> 1) & 3;
    int wn = (w & 1) ^ ((w >> 2) & 1);
    float acc[2][8][4] = {};

    int KT = K >> 5;
    for (int kc = 0; kc < KT; kc++) {
        *(uint4*)&Ash[arow][ak]     = vAh0;  *(uint4*)&Ash[arow][ak + 8] = vAh1;
        *(uint4*)&Asl[arow][ak]     = vAl0;  *(uint4*)&Asl[arow][ak + 8] = vAl1;
        *(uint4*)&Bsh[bk][bn]       = vBh0;  *(uint4*)&Bsh[bk][bn + 8]   = vBh1;
        *(uint4*)&Bsl[bk][bn]       = vBl0;  *(uint4*)&Bsl[bk][bn + 8]   = vBl1;
        __syncthreads();
        if (kc + 1 < KT) LOAD_CHUNK(kc + 1);

        #pragma unroll
        for (int s = 0; s < 2; s++) {
            unsigned ah[2][4], al[2][4];
            int arw = wm*32 + (lane & 15);
            int acl = s*16 + (lane >> 4)*8;
            ldmx4(ah[0], su32(&Ash[arw][acl]));
            ldmx4(al[0], su32(&Asl[arw][acl]));
            ldmx4(ah[1], su32(&Ash[arw + 16][acl]));
            ldmx4(al[1], su32(&Asl[arw + 16][acl]));
            int brow = s*16 + ((lane >> 3) & 1)*8 + (lane & 7);
            int bcol = wn*64 + (lane >> 4)*8;
            #pragma unroll
            for (int g = 0; g < 4; g++) {
                unsigned bh_[4], bl_[4];
                ldmx4t(bh_, su32(&Bsh[brow][bcol + g*16]));
                ldmx4t(bl_, su32(&Bsl[brow][bcol + g*16]));
                #pragma unroll
                for (int mt = 0; mt < 2; mt++) {
                    mma16816(acc[mt][2*g],   ah[mt], bh_);
                    mma16816(acc[mt][2*g],   ah[mt], bl_);
                    mma16816(acc[mt][2*g],   al[mt], bh_);
                    mma16816(acc[mt][2*g+1], ah[mt], bh_ + 2);
                    mma16816(acc[mt][2*g+1], ah[mt], bl_ + 2);
                    mma16816(acc[mt][2*g+1], al[mt], bh_ + 2);
                }
            }
        }
        __syncthreads();
    }
    #undef LOAD_CHUNK

    int rg = row0 + wm*32 + (lane >> 2);
    int cb = col0 + wn*64 + (lane & 3)*2;
    #pragma unroll
    for (int mt = 0; mt < 2; mt++) {
        #pragma unroll
        for (int n8 = 0; n8 < 8; n8++) {
            int rr = rg + mt*16;
            int cc = cb + n8*8;
            float v0 = acc[mt][n8][0], v1 = acc[mt][n8][1];
            float v2 = acc[mt][n8][2], v3 = acc[mt][n8][3];
            if (MODE != 7 && pbias) {
                float b0 = pbias[cc], b1 = pbias[cc+1];
                v0 += b0; v1 += b1; v2 += b0; v3 += b1;
            }
            if (MODE != 7 && p.act) { v0 = tanhf(v0); v1 = tanhf(v1); v2 = tanhf(v2); v3 = tanhf(v3); }
            if (rr < M) {
                *(float2*)(pC + (long)rr*ldc + cc) = make_float2(v0, v1);
                if (pChi) {
                    bf16 h0,l0,h1,l1; split2(v0,h0,l0); split2(v1,h1,l1);
                    *(__nv_bfloat162*)(pChi + (long)rr*ldc + cc) = __nv_bfloat162(h0, h1);
                    *(__nv_bfloat162*)(pClo + (long)rr*ldc + cc) = __nv_bfloat162(l0, l1);
                }
            }
            if (rr + 8 < M) {
                *(float2*)(pC + (long)(rr+8)*ldc + cc) = make_float2(v2, v3);
                if (pChi) {
                    bf16 h0,l0,h1,l1; split2(v2,h0,l0); split2(v3,h1,l1);
                    *(__nv_bfloat162*)(pChi + (long)(rr+8)*ldc + cc) = __nv_bfloat162(h0, h1);
                    *(__nv_bfloat162*)(pClo + (long)(rr+8)*ldc + cc) = __nv_bfloat162(l0, l1);
                }
            }
        }
    }
}

// epilogue: out = tanh(pA + pB + (EaX0+EaX1)[gather] + bias)
__global__ void k_pairepi(const float* __restrict__ part,
                          const float* __restrict__ EaA0, const float* __restrict__ EaA1,
                          const float* __restrict__ EaB0, const float* __restrict__ EaB1,
                          const float* __restrict__ b0p, const float* __restrict__ b1p,
                          const int* __restrict__ hts,
                          float* __restrict__ out0, float* __restrict__ out1)
{
    long idx = (long)blockIdx.x*256 + threadIdx.x;
    int pair = blockIdx.y;
    int d = (int)(idx % Dq); long n = idx / Dq;
    int b = (int)(n / Pq), pp = (int)(n % Pq);
    long eo = ((long)(b*NEq) + hts[pair*Pq + pp])*Dq + d;
    float ea = pair ? (EaB0[eo] + EaB1[eo]) : (EaA0[eo] + EaA1[eo]);
    const float* bi = pair ? b1p : b0p;
    float v = part[(long)(pair*2)*NPq*Dq + idx] + part[(long)(pair*2+1)*NPq*Dq + idx]
            + ea + bi[d];
    (pair ? out1 : out0)[idx] = tanhf(v);
}

// ---------------- rel head: fp16 2-term, 2 blocks/SM, 4-way K-split, atomic output ----
__global__ __launch_bounds__(256, 2)
void k_mma3(const __half* __restrict__ Wph, const __half* __restrict__ Wpl,
            const float* __restrict__ bhp, const float* __restrict__ btp,
            float* __restrict__ out)
{
    extern __shared__ char dynraw[];
    float* bhF = (float*)dynraw;
    float* btF = bhF + 128*68;
    __half* sAh = (__half*)(dynraw + 69632);
    __half* sBh = (__half*)(dynraw + 69632 + 10240);
    __half* sBl = (__half*)(dynraw + 69632 + 18944);

    int z = blockIdx.z;
    int h3 = z >> 2;
    int kcb = (z & 3) * 32;
    const __half* pBh = Wph + (long)h3*4096*128;
    const __half* pBl = Wpl + (long)h3*4096*128;
    int row0 = blockIdx.y * 128;
    int t = threadIdx.x;

    int arow = t >> 1;
    int ak   = (t & 1) * 16;
    int bk = t >> 3;
    int bn = (t & 7) * 16;

    for (int idx = t; idx < 128*16; idx += 256) {
        int r = idx >> 4, q = (idx & 15) * 4;
        int rr = row0 + r; if (rr >= NPq) rr = NPq - 1;
        *(float4*)&bhF[r*68 + q] = *(const float4*)(bhp + (long)rr*Dq + h3*64 + q);
        *(float4*)&btF[r*68 + q] = *(const float4*)(btp + (long)rr*Dq + h3*64 + q);
    }
    __syncthreads();

    uint4 vA0, vA1, vB0, vB1, vB2, vB3;

    #define LOAD_CHUNK3(kc) do {                                                    \
        int kk_ = (kc) + kcb;                                                       \
        int i_ = kk_ >> 1, j0_ = (kk_ & 1) * 32;                                    \
        float a_ = bhF[arow*68 + i_];                                               \
        const float* c_ = btF + arow*68 + j0_ + ak;                                 \
        union { uint4 u; __half2 h2[4]; } ua0, ua1;                                 \
        _Pragma("unroll")                                                           \
        for (int q = 0; q < 4; q++)                                                 \
            ua0.h2[q] = __float22half2_rn(make_float2(a_*c_[2*q], a_*c_[2*q+1]));   \
        _Pragma("unroll")                                                           \
        for (int q = 0; q < 4; q++)                                                 \
            ua1.h2[q] = __float22half2_rn(make_float2(a_*c_[8+2*q], a_*c_[8+2*q+1]));\
        vA0 = ua0.u; vA1 = ua1.u;                                                   \
        const __half* bp_ = pBh + (long)(kk_*32 + bk)*128 + bn;                     \
        const __half* bq_ = pBl + (long)(kk_*32 + bk)*128 + bn;                     \
        vB0 = *(const uint4*)bp_;  vB1 = *(const uint4*)(bp_ + 8);                  \
        vB2 = *(const uint4*)bq_;  vB3 = *(const uint4*)(bq_ + 8);                  \
    } while (0)

    LOAD_CHUNK3(0);

    int w = t >> 5, lane = t & 31;
    int wm = (w >> 1) & 3;
    int wn = (w & 1) ^ ((w >> 2) & 1);
    float acc[2][8][4] = {};

    for (int kc = 0; kc < 32; kc++) {
        *(uint4*)(sAh + arow*40 + ak)   = vA0;  *(uint4*)(sAh + arow*40 + ak + 8) = vA1;
        *(uint4*)(sBh + bk*136 + bn)    = vB0;  *(uint4*)(sBh + bk*136 + bn + 8)  = vB1;
        *(uint4*)(sBl + bk*136 + bn)    = vB2;  *(uint4*)(sBl + bk*136 + bn + 8)  = vB3;
        __syncthreads();
        if (kc + 1 < 32) LOAD_CHUNK3(kc + 1);

        #pragma unroll
        for (int s = 0; s < 2; s++) {
            unsigned ah[2][4];
            int arw = wm*32 + (lane & 15);
            int acl = s*16 + (lane >> 4)*8;
            ldmx4(ah[0], su32(sAh + arw*40 + acl));
            ldmx4(ah[1], su32(sAh + (arw + 16)*40 + acl));
            int brow = s*16 + ((lane >> 3) & 1)*8 + (lane & 7);
            int bcol = wn*64 + (lane >> 4)*8;
            #pragma unroll
            for (int g = 0; g < 4; g++) {
                if (wn == 1 && g == 3) continue;
                unsigned bh_[4], bl_[4];
                ldmx4t(bh_, su32(sBh + brow*136 + bcol + g*16));
                ldmx4t(bl_, su32(sBl + brow*136 + bcol + g*16));
                #pragma unroll
                for (int mt = 0; mt < 2; mt++) {
                    mma16816f(acc[mt][2*g],   ah[mt], bh_);
                    mma16816f(acc[mt][2*g],   ah[mt], bl_);
                    if (!(wn == 1 && g == 2)) {
                        mma16816f(acc[mt][2*g+1], ah[mt], bh_ + 2);
                        mma16816f(acc[mt][2*g+1], ah[mt], bl_ + 2);
                    }
                }
            }
        }
        __syncthreads();
    }
    #undef LOAD_CHUNK3

    int rg = row0 + wm*32 + (lane >> 2);
    int cb = wn*64 + (lane & 3)*2;
    #pragma unroll
    for (int mt = 0; mt < 2; mt++) {
        #pragma unroll
        for (int n8 = 0; n8 < 8; n8++) {
            int rr = rg + mt*16;
            int cc = cb + n8*8;
            if (cc >= Rq) continue;
            bool c1ok = (cc + 1) < Rq;
            if (rr < NPq) {
                atomicAdd(out + (long)rr*Rq + cc, acc[mt][n8][0]);
                if (c1ok) atomicAdd(out + (long)rr*Rq + cc + 1, acc[mt][n8][1]);
            }
            if (rr + 8 < NPq) {
                atomicAdd(out + (long)(rr+8)*Rq + cc, acc[mt][n8][2]);
                if (c1ok) atomicAdd(out + (long)(rr+8)*Rq + cc + 1, acc[mt][n8][3]);
            }
        }
    }
}

// ---------------- binary head: 16 rows per block ----------------
__global__ void k_gbl_bin16(const float* __restrict__ A, const float* __restrict__ C,
                            const float* __restrict__ W, const float* __restrict__ bias,
                            float* __restrict__ out, int* __restrict__ mask)
{
    extern __shared__ float sm[];
    float* a_s = sm;
    float* c_s = sm + 16*772;
    int n0 = blockIdx.x * 16;
    int t = threadIdx.x;
    for (int idx = t; idx < 16*192; idx += 256) {
        int r = idx / 192, q = (idx % 192) * 4;
        *(float4*)&a_s[r*772 + q] = *(const float4*)(A + (long)(n0 + r)*Dq + q);
        *(float4*)&c_s[r*772 + q] = *(const float4*)(C + (long)(n0 + r)*Dq + q);
    }
    __syncthreads();
    int nl = t & 15, grp = t >> 4;
    float s0 = 0.f, s1 = 0.f;
    for (int s = 0; s < 48; s++) {
        int hi = grp*48 + s;
        float ai = a_s[nl*772 + hi];
        const float2* w2 = (const float2*)(W + (long)hi*BSq*2);
        const float* cc = c_s + nl*772 + (hi & ~63);
        #pragma unroll 8
        for (int j = 0; j < BSq; j++) {
            float v = ai * cc[j];
            float2 ww = w2[j];
            s0 += v*ww.x; s1 += v*ww.y;
        }
    }
    __shared__ float r0[16][17], r1[16][17];
    r0[grp][nl] = s0; r1[grp][nl] = s1;
    __syncthreads();
    if (t < 16) {
        float b0 = bias[0], b1 = bias[1];
        #pragma unroll
        for (int g = 0; g < 16; g++) { b0 += r0[g][t]; b1 += r1[g][t]; }
        int n = n0 + t;
        out[n*2] = b0; out[n*2+1] = b1;
        mask[n] = (b1 > b0) ? 1 : 0;
    }
}

__global__ void k_inc(const int* __restrict__ hts, int* __restrict__ inc)
{
    if (threadIdx.x == 0 && blockIdx.x == 0) {
        int cnt[NEq];
        for (int i = 0; i < NEq; i++) cnt[i] = 0;
        for (int p = 0; p < Pq; p++) {
            int d = hts[Pq + p];
            inc[d*23 + cnt[d]++] = p;
        }
    }
}

__global__ void k_fscore(const float* __restrict__ Ni, const float* __restrict__ Nj,
                         const float* __restrict__ EfW, const float* __restrict__ eb,
                         const float* __restrict__ attn_p, const int* __restrict__ mask,
                         const int* __restrict__ hts,
                         float* __restrict__ f, float* __restrict__ score)
{
    __shared__ float f_s[Dq];
    int be = blockIdx.x; int b = be / Eq, e = be % Eq;
    int src, dst; const float* ef = 0;
    if (e < Pq) { src = hts[e]; dst = hts[Pq + e]; ef = EfW + ((long)b*Pq + e)*Dq; }
    else        { src = dst = e - Pq; }
    const float* ni = Ni + ((long)b*NEq + src)*Dq;
    const float* nj = Nj + ((long)b*NEq + dst)*Dq;
    float* o = f + (long)be*Dq;
    int t = threadIdx.x;
    for (int d = t; d < Dq; d += 384) {
        float v = ni[d] + nj[d] + eb[d];
        if (ef) v += ef[d];
        f_s[d] = v;
        o[d] = v;
    }
    __syncthreads();
    int h = t >> 5, lane = t & 31;
    const float* fr = f_s + h*BSq;
    float s = 0.f;
    #pragma unroll
    for (int i = lane; i < BSq; i += 32) {
        float x = fr[i];
        float lr = x > 0.f ? x : 0.2f*x;
        s += lr * attn_p[h*BSq + i];
    }
    #pragma unroll
    for (int off = 16; off; off >>= 1) s += __shfl_xor_sync(0xffffffffu, s, off);
    if (lane == 0) {
        int m = (e < Pq) ? mask[b*Pq + e] : 1;
        score[(long)be*Hq + h] = m ? s : -1e30f;
    }
}

__global__ void k_soft(const float* __restrict__ score, const int* __restrict__ inc,
                       const int* __restrict__ mask, float* __restrict__ alpha)
{
    int bn = blockIdx.x; int b = bn / NEq, n = bn % NEq;
    int h = threadIdx.x >> 5, lane = threadIdx.x & 31;
    int eid = 0; float sc = -INFINITY; float m = 0.f;
    if (lane < 24) {
        eid = (lane < 23) ? inc[n*23 + lane] : (Pq + n);
        sc  = score[((long)b*Eq + eid)*Hq + h];
        m   = (eid < Pq) ? (float)mask[b*Pq + eid] : 1.f;
    }
    float mx = sc;
    #pragma unroll
    for (int off = 16; off; off >>= 1) mx = fmaxf(mx, __shfl_xor_sync(0xffffffffu, mx, off));
    float ex = (lane < 24) ? expf(sc - mx)*m : 0.f;
    float den = ex;
    #pragma unroll
    for (int off = 16; off; off >>= 1) den += __shfl_xor_sync(0xffffffffu, den, off);
    if (lane < 24) alpha[((long)b*Eq + eid)*Hq + h] = ex / (den + 1e-20f);
}

__global__ void k_nodeout(const float* __restrict__ alpha, const float* __restrict__ Hsrc,
                          const int* __restrict__ inc, const int* __restrict__ hts,
                          bf16* __restrict__ oh, bf16* __restrict__ ol)
{
    int bn = blockIdx.x; int b = bn / NEq, n = bn % NEq;
    __shared__ int   esrc[24];
    __shared__ float eal[24*Hq];
    int t = threadIdx.x;
    if (t < 24) {
        int eid = (t < 23) ? inc[n*23 + t] : (Pq + n);
        esrc[t] = (t < 23) ? hts[eid] : n;
    }
    for (int t2 = t; t2 < 24*Hq; t2 += blockDim.x) {
        int slot = t2 / Hq, hh = t2 % Hq;
        int eid = (slot < 23) ? inc[n*23 + slot] : (Pq + n);
        eal[t2] = alpha[((long)b*Eq + eid)*Hq + hh];
    }
    __syncthreads();
    for (int d = t; d < Dq; d += blockDim.x) {
        int h = d >> 6;
        float s = 0.f;
        #pragma unroll
        for (int slot = 0; slot < 24; slot++)
            s += eal[slot*Hq + h] * Hsrc[((long)b*NEq + esrc[slot])*Dq + d];
        bf16 hh, ll; split2(s, hh, ll);
        oh[(long)bn*Dq + d] = hh; ol[(long)bn*Dq + d] = ll;
    }
}

__global__ void k_newci(const int* __restrict__ mask, const float* __restrict__ f,
                        const float* __restrict__ ci, bf16* __restrict__ oh,
                        bf16* __restrict__ ol)
{
    long idx = (long)blockIdx.x*256 + threadIdx.x;
    int d = (int)(idx % Dq); long n = idx / Dq;
    int b = (int)(n / Pq), p = (int)(n % Pq);
    float v = mask[n] ? f[((long)b*Eq + p)*Dq + d] : ci[idx];
    bf16 h, l; split2(v, h, l);
    oh[idx] = h; ol[idx] = l;
}

// ---------------- host ----------------
template <typename T>
static T* sym(const void* s) { void* p = 0; cudaGetSymbolAddress(&p, s); return (T*)p; }

#define SMEM_REL 97280

extern "C" void kernel_launch(void* const* d_in, const int* in_sizes, int n_in,
                              void* d_out, int out_size)
{
    const float* ctx    = (const float*)d_in[0];
    const float* att    = (const float*)d_in[1];
    const int*   mm     = (const int*)  d_in[2];
    const float* em     = (const float*)d_in[3];
    const int*   hts    = (const int*)  d_in[4];
    const float* Whb    = (const float*)d_in[5];
    const float* bhb    = (const float*)d_in[6];
    const float* Wtb    = (const float*)d_in[7];
    const float* btb    = (const float*)d_in[8];
    const float* Wbin   = (const float*)d_in[9];
    const float* bbin   = (const float*)d_in[10];
    const float* Wrel   = (const float*)d_in[11];
    const float* brel   = (const float*)d_in[12];
    const float* Wh     = (const float*)d_in[13];
    const float* bh     = (const float*)d_in[14];
    const float* Wt     = (const float*)d_in[15];
    const float* bt     = (const float*)d_in[16];
    const float* Wnode  = (const float*)d_in[17];
    const float* Wni    = (const float*)d_in[18];
    const float* Wfij   = (const float*)d_in[19];
    const float* Wnj    = (const float*)d_in[20];
    const float* attn_p = (const float*)d_in[21];
    const float* egat_b = (const float*)d_in[22];

    float* outBin = (float*)d_out;
    float* outRel = outBin + (long)NPq*2;

    float* p_cur   = sym<float>(g_cur);
    float* p_ci    = sym<float>(g_ci);
    float* p_bh    = sym<float>(g_bh);
    float* p_bt    = sym<float>(g_bt);
    int*   p_mask  = sym<int>(g_mask);
    float* p_Ni    = sym<float>(g_Ni);
    float* p_Nj    = sym<float>(g_Nj);
    float* p_Hs    = sym<float>(g_Hs);
    float* p_EfW   = sym<float>(g_EfW);
    float* p_f     = sym<float>(g_f);
    float* p_score = sym<float>(g_score);
    float* p_alpha = sym<float>(g_alpha);
    float* p_ppart = sym<float>(g_pairpart);
    int*   p_inc   = sym<int>(g_inc);
    float* p_EA0   = sym<float>(g_EA0);
    float* p_EA1   = sym<float>(g_EA1);
    float* p_EB0   = sym<float>(g_EB0);
    float* p_EB1   = sym<float>(g_EB1);

    bf16 *enth = sym<bf16>(g_enth), *entl = sym<bf16>(g_entl);
    bf16 *cah  = sym<bf16>(g_cah),  *cal  = sym<bf16>(g_cal);
    bf16 *cih  = sym<bf16>(g_cih),  *cil  = sym<bf16>(g_cil);
    bf16 *nouth= sym<bf16>(g_nouth),*noutl= sym<bf16>(g_noutl);
    bf16 *nch  = sym<bf16>(g_nch),  *ncl  = sym<bf16>(g_ncl);
    bf16 *ctxh = sym<bf16>(g_ctxh), *ctxl = sym<bf16>(g_ctxl);
    bf16 *Whbh = sym<bf16>(g_Whbh), *Whbl = sym<bf16>(g_Whbl);
    bf16 *Wtbh = sym<bf16>(g_Wtbh), *Wtbl = sym<bf16>(g_Wtbl);
    bf16 *Whh  = sym<bf16>(g_Whh),  *Whl  = sym<bf16>(g_Whl);
    bf16 *Wth  = sym<bf16>(g_Wth),  *Wtl  = sym<bf16>(g_Wtl);
    bf16 *Wfijh= sym<bf16>(g_Wfijh),*Wfijl= sym<bf16>(g_Wfijl);
    bf16 *Wnih = sym<bf16>(g_Wnih), *Wnil = sym<bf16>(g_Wnil);
    bf16 *Wnjh = sym<bf16>(g_Wnjh), *Wnjl = sym<bf16>(g_Wnjl);
    bf16 *Wnodeh=sym<bf16>(g_Wnodeh),*Wnodel=sym<bf16>(g_Wnodel);
    __half *Wpadh = sym<__half>(g_Wpadh), *Wpadl = sym<__half>(g_Wpadl);

    cudaFuncSetAttribute(k_mma3, cudaFuncAttributeMaxDynamicSharedMemorySize, SMEM_REL);
    cudaFuncSetAttribute(k_gbl_bin16, cudaFuncAttributeMaxDynamicSharedMemorySize, 2*16*772*4);

    static cudaStream_t s1 = 0, s2 = 0;
    static cudaEvent_t ev0 = 0, ev1 = 0, ev2 = 0, ev3 = 0, ev4 = 0, ev5 = 0, ev6 = 0;
    if (!s1) {
        cudaStreamCreateWithFlags(&s1, cudaStreamNonBlocking);
        cudaStreamCreateWithFlags(&s2, cudaStreamNonBlocking);
        cudaEventCreateWithFlags(&ev0, cudaEventDisableTiming);
        cudaEventCreateWithFlags(&ev1, cudaEventDisableTiming);
        cudaEventCreateWithFlags(&ev2, cudaEventDisableTiming);
        cudaEventCreateWithFlags(&ev3, cudaEventDisableTiming);
        cudaEventCreateWithFlags(&ev4, cudaEventDisableTiming);
        cudaEventCreateWithFlags(&ev5, cudaEventDisableTiming);
        cudaEventCreateWithFlags(&ev6, cudaEventDisableTiming);
    }

    // ---- fork 1: ctx split + weight conversions on s1 ----
    cudaEventRecord(ev0, 0);
    cudaStreamWaitEvent(s1, ev0, 0);
    k_split<<<(int)(((long)Bq*Lq*Dq + 255)/256), 256, 0, s1>>>(ctx, ctxh, ctxl, (long)Bq*Lq*Dq);
    cudaEventRecord(ev6, s1);
    {
        SplitP sp = {};
        sp.s[0] = Whb; sp.h[0] = Whbh; sp.l[0] = Whbl;
        sp.s[1] = Wtb; sp.h[1] = Wtbh; sp.l[1] = Wtbl;
        sp.s[2] = Wh;  sp.h[2] = Whh;  sp.l[2] = Whl;
        sp.s[3] = Wt;  sp.h[3] = Wth;  sp.l[3] = Wtl;
        k_split4<<<dim3((2*Dq*Dq + 255)/256, 4), 256, 0, s1>>>(sp, (long)2*Dq*Dq);
    }
    {
        SplitP sp = {};
        sp.s[0] = Wfij;  sp.h[0] = Wfijh;  sp.l[0] = Wfijl;
        sp.s[1] = Wni;   sp.h[1] = Wnih;   sp.l[1] = Wnil;
        sp.s[2] = Wnj;   sp.h[2] = Wnjh;   sp.l[2] = Wnjl;
        sp.s[3] = Wnode; sp.h[3] = Wnodeh; sp.l[3] = Wnodel;
        k_split4<<<dim3((Dq*Dq + 255)/256, 4), 256, 0, s1>>>(sp, (long)Dq*Dq);
    }
    k_wpadsplit<<<(int)(((long)Hq*4096*128)/256), 256, 0, s1>>>(Wrel, Wpadh, Wpadl);
    cudaEventRecord(ev1, s1);

    // ---- main: pooling + outRel bias init ----
    k_binit<<<(int)(((long)NPq*Rq + 255)/256), 256>>>(brel, outRel);
    k_entity<<<Bq*NEq, 256>>>(ctx, mm, em, enth, entl);
    k_cur<<<Bq*Hq*NEq, 256>>>(att, mm, em, p_cur);
    k_ca<<<Bq*Pq, 256>>>(p_cur, hts, cah, cal);
    k_inc<<<1, 32>>>(hts, p_inc);

    // ---- ci = ca @ ctx ----
    cudaStreamWaitEvent(0, ev6, 0);
    {
        GemmP g = {};
        for (int z = 0; z < Bq; z++) {
            g.Ah[z] = cah + (long)z*Pq*Lq;  g.Al[z] = cal + (long)z*Pq*Lq;
            g.Bh[z] = ctxh + (long)z*Lq*Dq; g.Bl[z] = ctxl + (long)z*Lq*Dq;
            g.C[z]  = p_ci + (long)z*Pq*Dq;
            g.Chi[z]= cih  + (long)z*Pq*Dq; g.Clo[z]= cil + (long)z*Pq*Dq;
            g.Mz[z] = Pq;
        }
        g.K = Lq; g.lda = Lq; g.ldb = Dq; g.ldc = Dq; g.splitout = 1;
        k_mma<0><<<dim3(6, 5, 4), 256>>>(g);
    }

    // join weights; fork 2: EGAT GEMM on s2 concurrent with bin chain
    cudaStreamWaitEvent(0, ev1, 0);
    cudaEventRecord(ev2, 0);
    cudaStreamWaitEvent(s2, ev2, 0);
    {
        GemmP g = {};
        g.Ah[0] = cih;  g.Al[0] = cil;  g.Bh[0] = Wfijh;  g.Bl[0] = Wfijl;  g.C[0] = p_EfW; g.Mz[0] = NPq;
        g.Ah[1] = enth; g.Al[1] = entl; g.Bh[1] = Wnih;   g.Bl[1] = Wnil;   g.C[1] = p_Ni;  g.Mz[1] = Bq*NEq;
        g.Ah[2] = enth; g.Al[2] = entl; g.Bh[2] = Wnjh;   g.Bl[2] = Wnjl;   g.C[2] = p_Nj;  g.Mz[2] = Bq*NEq;
        g.Ah[3] = enth; g.Al[3] = entl; g.Bh[3] = Wnodeh; g.Bl[3] = Wnodel; g.C[3] = p_Hs;  g.Mz[3] = Bq*NEq;
        g.K = Dq; g.lda = Dq; g.ldb = Dq; g.ldc = Dq;
        k_mma<0><<<dim3(6, 18, 4), 256, 0, s2>>>(g);
    }
    cudaEventRecord(ev3, s2);

    // ---- main: bin chain (MODE7: pair partials z0..3 + Ebin partials z4..7) ----
    {
        GemmP g = {};
        g.Ah[0] = cih;  g.Al[0] = cil;  g.Bh[0] = Whbh + (long)Dq*Dq; g.Bl[0] = Whbl + (long)Dq*Dq; g.Mz[0] = NPq;
        g.Ah[1] = cih;  g.Al[1] = cil;  g.Bh[1] = Wtbh + (long)Dq*Dq; g.Bl[1] = Wtbl + (long)Dq*Dq; g.Mz[1] = NPq;
        g.Ah[2] = enth; g.Al[2] = entl; g.Bh[2] = Whbh; g.Bl[2] = Whbl; g.Mz[2] = Bq*NEq;
        g.Ah[3] = enth; g.Al[3] = entl; g.Bh[3] = Wtbh; g.Bl[3] = Wtbl; g.Mz[3] = Bq*NEq;
        for (int z = 0; z < 4; z++) g.C[z] = p_ppart + (long)z*NPq*Dq;
        g.C[4] = p_EA0; g.C[5] = p_EA1; g.C[6] = p_EB0; g.C[7] = p_EB1;
        g.K = 384; g.lda = Dq; g.ldb = Dq; g.ldc = Dq;
        k_mma<7><<<dim3(6, 18, 8), 256>>>(g);
    }
    k_pairepi<<<dim3((int)(((long)NPq*Dq)/256), 2), 256>>>(p_ppart, p_EA0, p_EA1, p_EB0, p_EB1, bhb, btb, hts, p_bh, p_bt);
    k_gbl_bin16<<<NPq/16, 256, 2*16*772*4>>>(p_bh, p_bt, Wbin, bbin, outBin, p_mask);

    // join EGAT
    cudaStreamWaitEvent(0, ev3, 0);
    k_fscore<<<Bq*Eq, 384>>>(p_Ni, p_Nj, p_EfW, egat_b, attn_p, p_mask, hts, p_f, p_score);
    // fork 3: newci on s2 concurrent with soft/nodeout
    cudaEventRecord(ev4, 0);
    cudaStreamWaitEvent(s2, ev4, 0);
    k_newci<<<NPq*Dq/256, 256, 0, s2>>>(p_mask, p_f, p_ci, nch, ncl);
    cudaEventRecord(ev5, s2);

    k_soft<<<Bq*NEq, 384>>>(p_score, p_inc, p_mask, p_alpha);
    k_nodeout<<<Bq*NEq, 256>>>(p_alpha, p_Hs, p_inc, hts, nouth, noutl);
    cudaStreamWaitEvent(0, ev5, 0);

    // ---- rel pair (MODE7: pair partials + Er partials) + epilogue ----
    {
        GemmP g = {};
        g.Ah[0] = nch;   g.Al[0] = ncl;   g.Bh[0] = Whh + (long)Dq*Dq; g.Bl[0] = Whl + (long)Dq*Dq; g.Mz[0] = NPq;
        g.Ah[1] = nch;   g.Al[1] = ncl;   g.Bh[1] = Wth + (long)Dq*Dq; g.Bl[1] = Wtl + (long)Dq*Dq; g.Mz[1] = NPq;
        g.Ah[2] = nouth; g.Al[2] = noutl; g.Bh[2] = Whh; g.Bl[2] = Whl; g.Mz[2] = Bq*NEq;
        g.Ah[3] = nouth; g.Al[3] = noutl; g.Bh[3] = Wth; g.Bl[3] = Wtl; g.Mz[3] = Bq*NEq;
        for (int z = 0; z < 4; z++) g.C[z] = p_ppart + (long)z*NPq*Dq;
        g.C[4] = p_EA0; g.C[5] = p_EA1; g.C[6] = p_EB0; g.C[7] = p_EB1;
        g.K = 384; g.lda = Dq; g.ldb = Dq; g.ldc = Dq;
        k_mma<7><<<dim3(6, 18, 8), 256>>>(g);
    }
    k_pairepi<<<dim3((int)(((long)NPq*Dq)/256), 2), 256>>>(p_ppart, p_EA0, p_EA1, p_EB0, p_EB1, bh, bt, hts, p_bh, p_bt);

    // ---- rel head: atomic-accumulate into outRel (pre-initialized with brel) ----
    k_mma3<<<dim3(1, 18, 48), 256, SMEM_REL>>>(Wpadh, Wpadl, p_bh, p_bt, outRel);
}